// round 12
// baseline (speedup 1.0000x reference)
#include <cuda_runtime.h>
#include <cuda_bf16.h>
#include <cuda_fp16.h>
#include <cstdint>
#include <math.h>

#define LSEQ 4096
#define BATCH 2
#define DIMC 256
#define EPS_F 1e-5f
#define SCN_ (64*BATCH*DIMC*8)

// ---------------- scratch (device globals) ----------------
__device__ float g_x   [BATCH*DIMC*LSEQ];
__device__ float g_z   [BATCH*DIMC*LSEQ];
__device__ float g_xc  [2][BATCH*DIMC*LSEQ];
__device__ float g_dbl [2][BATCH*32*LSEQ];
__device__ float g_dt  [2][BATCH*DIMC*LSEQ];
__device__ float g_P   [2][SCN_];
__device__ float g_S   [2][SCN_];
__device__ float g_Hi  [2][SCN_];
__device__ float g_y   [2][BATCH*DIMC*LSEQ];
__device__ float g_skipT[BATCH*LSEQ*DIMC];

__device__ __nv_bfloat16 g_s0h[BATCH*LSEQ*DIMC], g_s0l[BATCH*LSEQ*DIMC];
__device__ __nv_bfloat16 g_s1h[BATCH*LSEQ*DIMC], g_s1l[BATCH*LSEQ*DIMC];
__device__ __nv_bfloat16 g_ynh[6*LSEQ*DIMC],     g_ynl[6*LSEQ*DIMC];
__device__ __half        g_of [6*LSEQ*DIMC];          // out_proj(+skip) result, fp16
__device__ __nv_bfloat16 g_wip_h[DIMC*DIMC], g_wip_l[DIMC*DIMC];
__device__ __nv_bfloat16 g_wiz_h[DIMC*DIMC], g_wiz_l[DIMC*DIMC];
__device__ __nv_bfloat16 g_wop_h[DIMC*DIMC], g_wop_l[DIMC*DIMC];
__device__ __half        g_wc3f[1200*DIMC];           // conv3d weight, fp16

__device__ __forceinline__ float sigmoidf_(float x){ return 1.f/(1.f+__expf(-x)); }
__device__ __forceinline__ float softplusf_(float x){ return x>20.f ? x : log1pf(__expf(x)); }

__device__ __forceinline__ void bf16split(float v, __nv_bfloat16& h, __nv_bfloat16& l) {
    h = __float2bfloat16(v);
    l = __float2bfloat16(v - __bfloat162float(h));
}

__device__ __forceinline__ uint32_t smem_u32(const void* p) {
    uint32_t a;
    asm("{ .reg .u64 t; cvta.to.shared.u64 t, %1; cvt.u32.u64 %0, t; }" : "=r"(a) : "l"(p));
    return a;
}
__device__ __forceinline__ void ldmx4(uint32_t* r, uint32_t addr) {
    asm volatile("ldmatrix.sync.aligned.m8n8.x4.shared.b16 {%0,%1,%2,%3}, [%4];"
        : "=r"(r[0]),"=r"(r[1]),"=r"(r[2]),"=r"(r[3]) : "r"(addr));
}
__device__ __forceinline__ void mma16816(float* d, const uint32_t* a, uint32_t b0, uint32_t b1) {
    asm volatile("mma.sync.aligned.m16n8k16.row.col.f32.bf16.bf16.f32 "
        "{%0,%1,%2,%3}, {%4,%5,%6,%7}, {%8,%9}, {%0,%1,%2,%3};"
        : "+f"(d[0]),"+f"(d[1]),"+f"(d[2]),"+f"(d[3])
        : "r"(a[0]),"r"(a[1]),"r"(a[2]),"r"(a[3]), "r"(b0),"r"(b1));
}
__device__ __forceinline__ void mma16816h(float* d, const uint32_t* a, uint32_t b0, uint32_t b1) {
    asm volatile("mma.sync.aligned.m16n8k16.row.col.f32.f16.f16.f32 "
        "{%0,%1,%2,%3}, {%4,%5,%6,%7}, {%8,%9}, {%0,%1,%2,%3};"
        : "+f"(d[0]),"+f"(d[1]),"+f"(d[2]),"+f"(d[3])
        : "r"(a[0]),"r"(a[1]),"r"(a[2]),"r"(a[3]), "r"(b0),"r"(b1));
}
__device__ __forceinline__ void cp16(uint32_t dst, const void* src, int sz) {
    asm volatile("cp.async.cg.shared.global [%0], [%1], 16, %2;"
        :: "r"(dst), "l"(__cvta_generic_to_global(src)), "r"(sz) : "memory");
}

// ---------------- split-bf16 GEMM (3-pass), cp.async double-buffered, 128x64 ----------------
#define EPT_XPOSE 0
#define EPT_SKIP  1
#define TILE_A  18432            // 128 rows x 72 halves x 2B
#define TILE_BB 9216             // 64 rows x 72 halves x 2B
#define STG     (2*TILE_A + 2*TILE_BB)   // 55296

template<int EPT>
__global__ void __launch_bounds__(256, 2) tcgemm_k(
    const __nv_bfloat16* __restrict__ Ah, const __nv_bfloat16* __restrict__ Al,
    const __nv_bfloat16* __restrict__ Bh, const __nv_bfloat16* __restrict__ Bl,
    int bRows,
    float* __restrict__ outF,
    const float* __restrict__ skipT,
    __half* __restrict__ Of)
{
    extern __shared__ char smem[];
    const int tid = threadIdx.x, lane = tid & 31, warp = tid >> 5;
    const int mw = warp & 3, nw = warp >> 2;
    const int n0 = blockIdx.x * 64, tl0 = blockIdx.y * 128, zb = blockIdx.z;
    const long long t0 = (long long)zb * LSEQ + tl0;

    float acc[2][4][4];
    #pragma unroll
    for (int i = 0; i < 2; i++)
        #pragma unroll
        for (int j = 0; j < 4; j++)
            #pragma unroll
            for (int c = 0; c < 4; c++) acc[i][j][c] = 0.f;

    const uint32_t sbase = smem_u32(smem);
    const int a_row  = (lane & 7) + ((lane >> 3) & 1) * 8;
    const int a_kadd = (lane >> 4) * 8;
    const int b_row  = (lane & 7) + (lane >> 4) * 8;
    const int b_kadd = ((lane >> 3) & 1) * 8;
    const uint32_t aoffH = sbase + 0        + (uint32_t)((mw*32 + a_row)*72 + a_kadd) * 2;
    const uint32_t boffH = sbase + 2*TILE_A + (uint32_t)((nw*32 + b_row)*72 + b_kadd) * 2;

    const int lrow = tid >> 3, lc8 = (tid & 7) * 8;

    auto load_chunk = [&](int kc, int stage) {
        const int kofs = kc * 64;
        const uint32_t sb0 = sbase + stage * STG;
        #pragma unroll
        for (int it = 0; it < 4; it++) {
            int row = lrow + it * 32;
            uint32_t sa = sb0 + (uint32_t)(row * 72 + lc8) * 2;
            cp16(sa,          Ah + (t0 + row) * 256 + kofs + lc8, 16);
            cp16(sa + TILE_A, Al + (t0 + row) * 256 + kofs + lc8, 16);
        }
        #pragma unroll
        for (int it = 0; it < 2; it++) {
            int row = lrow + it * 32;
            uint32_t sa = sb0 + 2*TILE_A + (uint32_t)(row * 72 + lc8) * 2;
            int brow = n0 + row;
            int ok = (brow < bRows) ? 16 : 0;
            if (brow >= bRows) brow = bRows - 1;
            cp16(sa,           Bh + (size_t)brow * 256 + kofs + lc8, ok);
            cp16(sa + TILE_BB, Bl + (size_t)brow * 256 + kofs + lc8, ok);
        }
    };

    auto compute = [&](int stage) {
        const uint32_t sadd = (uint32_t)stage * STG;
        #pragma unroll
        for (int ks = 0; ks < 4; ks++) {
            const uint32_t k2 = (uint32_t)(ks * 16) * 2;
            uint32_t aH[2][4], aL[2][4];
            #pragma unroll
            for (int i = 0; i < 2; i++) {
                ldmx4(aH[i], aoffH + sadd + i*16*144 + k2);
                ldmx4(aL[i], aoffH + sadd + TILE_A + i*16*144 + k2);
            }
            uint32_t bH[2][4], bL[2][4];
            #pragma unroll
            for (int g = 0; g < 2; g++) {
                ldmx4(bH[g], boffH + sadd + g*16*144 + k2);
                ldmx4(bL[g], boffH + sadd + TILE_BB + g*16*144 + k2);
            }
            #pragma unroll
            for (int i = 0; i < 2; i++)
                #pragma unroll
                for (int g = 0; g < 2; g++)
                    #pragma unroll
                    for (int p = 0; p < 2; p++) {
                        int j4 = g*2 + p;
                        mma16816(acc[i][j4], aH[i], bH[g][2*p], bH[g][2*p+1]);
                        mma16816(acc[i][j4], aH[i], bL[g][2*p], bL[g][2*p+1]);
                        mma16816(acc[i][j4], aL[i], bH[g][2*p], bH[g][2*p+1]);
                    }
        }
    };

    load_chunk(0, 0);
    asm volatile("cp.async.commit_group;" ::: "memory");
    for (int kc = 0; kc < 4; kc++) {
        if (kc < 3) {
            load_chunk(kc + 1, (kc + 1) & 1);
            asm volatile("cp.async.commit_group;" ::: "memory");
            asm volatile("cp.async.wait_group 1;" ::: "memory");
        } else {
            asm volatile("cp.async.wait_group 0;" ::: "memory");
        }
        __syncthreads();
        compute(kc & 1);
        __syncthreads();
    }

    if (EPT == EPT_SKIP) {
        // o = acc + skip -> single fp16, token-major
        #pragma unroll
        for (int i = 0; i < 2; i++)
            #pragma unroll
            for (int rr = 0; rr < 2; rr++) {
                int tok = tl0 + mw*32 + i*16 + (lane >> 2) + rr*8;
                size_t orow = ((size_t)zb * LSEQ + tok) * 256;
                size_t srow = ((size_t)(zb & 1) * LSEQ + tok) * 256;
                #pragma unroll
                for (int j4 = 0; j4 < 4; j4++) {
                    int n = n0 + nw*32 + j4*8 + 2*(lane & 3);
                    float2 sk = *(const float2*)(skipT + srow + n);
                    __half2 hv;
                    hv.x = __float2half(acc[i][j4][rr*2+0] + sk.x);
                    hv.y = __float2half(acc[i][j4][rr*2+1] + sk.y);
                    *(__half2*)(Of + orow + n) = hv;
                }
            }
    } else {
        // channel-major fp32 via smem transpose
        float* sbuf = (float*)smem;
        __syncthreads();
        #pragma unroll
        for (int i = 0; i < 2; i++)
            #pragma unroll
            for (int j4 = 0; j4 < 4; j4++)
                #pragma unroll
                for (int rr = 0; rr < 2; rr++) {
                    int tok = mw*32 + i*16 + (lane >> 2) + rr*8;
                    int nl = nw*32 + j4*8 + 2*(lane & 3);
                    sbuf[nl*132 + tok]     = acc[i][j4][rr*2+0];
                    sbuf[(nl+1)*132 + tok] = acc[i][j4][rr*2+1];
                }
        __syncthreads();
        int row = tid >> 2;
        int n = n0 + row;
        if (n < bRows) {
            const float* srcr = sbuf + row*132;
            float* dstr = outF + ((size_t)zb * bRows + n) * LSEQ + tl0;
            int c0 = (tid & 3) * 4;
            #pragma unroll
            for (int q = 0; q < 8; q++) {
                int col = c0 + q*16;
                *(float4*)(dstr + col) = *(const float4*)(srcr + col);
            }
        }
    }
}

// ---------------- single-pass fp16 GEMM (conv3d), cp.async double-buffered ----------------
#define STGH (TILE_A + TILE_BB)   // 27648

__global__ void __launch_bounds__(256, 2) tcgemmH_k(
    const __half* __restrict__ A, const __half* __restrict__ W, int bRows,
    float* __restrict__ outF, const float* __restrict__ bias)
{
    extern __shared__ char smem[];
    const int tid = threadIdx.x, lane = tid & 31, warp = tid >> 5;
    const int mw = warp & 3, nw = warp >> 2;
    const int n0 = blockIdx.x * 64, tl0 = blockIdx.y * 128, zb = blockIdx.z;
    const long long t0 = (long long)zb * LSEQ + tl0;

    float acc[2][4][4];
    #pragma unroll
    for (int i = 0; i < 2; i++)
        #pragma unroll
        for (int j = 0; j < 4; j++)
            #pragma unroll
            for (int c = 0; c < 4; c++) acc[i][j][c] = 0.f;

    const uint32_t sbase = smem_u32(smem);
    const int a_row  = (lane & 7) + ((lane >> 3) & 1) * 8;
    const int a_kadd = (lane >> 4) * 8;
    const int b_row  = (lane & 7) + (lane >> 4) * 8;
    const int b_kadd = ((lane >> 3) & 1) * 8;
    const uint32_t aoff = sbase + 0      + (uint32_t)((mw*32 + a_row)*72 + a_kadd) * 2;
    const uint32_t boff = sbase + TILE_A + (uint32_t)((nw*32 + b_row)*72 + b_kadd) * 2;

    const int lrow = tid >> 3, lc8 = (tid & 7) * 8;

    auto load_chunk = [&](int kc, int stage) {
        const int kofs = kc * 64;
        const uint32_t sb0 = sbase + stage * STGH;
        #pragma unroll
        for (int it = 0; it < 4; it++) {
            int row = lrow + it * 32;
            cp16(sb0 + (uint32_t)(row * 72 + lc8) * 2, A + (t0 + row) * 256 + kofs + lc8, 16);
        }
        #pragma unroll
        for (int it = 0; it < 2; it++) {
            int row = lrow + it * 32;
            int brow = n0 + row;
            int ok = (brow < bRows) ? 16 : 0;
            if (brow >= bRows) brow = bRows - 1;
            cp16(sb0 + TILE_A + (uint32_t)(row * 72 + lc8) * 2,
                 W + (size_t)brow * 256 + kofs + lc8, ok);
        }
    };

    auto compute = [&](int stage) {
        const uint32_t sadd = (uint32_t)stage * STGH;
        #pragma unroll
        for (int ks = 0; ks < 4; ks++) {
            const uint32_t k2 = (uint32_t)(ks * 16) * 2;
            uint32_t aF[2][4], bF[2][4];
            #pragma unroll
            for (int i = 0; i < 2; i++) ldmx4(aF[i], aoff + sadd + i*16*144 + k2);
            #pragma unroll
            for (int g = 0; g < 2; g++) ldmx4(bF[g], boff + sadd + g*16*144 + k2);
            #pragma unroll
            for (int i = 0; i < 2; i++)
                #pragma unroll
                for (int g = 0; g < 2; g++)
                    #pragma unroll
                    for (int p = 0; p < 2; p++)
                        mma16816h(acc[i][g*2+p], aF[i], bF[g][2*p], bF[g][2*p+1]);
        }
    };

    load_chunk(0, 0);
    asm volatile("cp.async.commit_group;" ::: "memory");
    for (int kc = 0; kc < 4; kc++) {
        if (kc < 3) {
            load_chunk(kc + 1, (kc + 1) & 1);
            asm volatile("cp.async.commit_group;" ::: "memory");
            asm volatile("cp.async.wait_group 1;" ::: "memory");
        } else {
            asm volatile("cp.async.wait_group 0;" ::: "memory");
        }
        __syncthreads();
        compute(kc & 1);
        __syncthreads();
    }

    // channel-major fp32 + bias via smem transpose
    float* sbuf = (float*)smem;
    __syncthreads();
    #pragma unroll
    for (int i = 0; i < 2; i++)
        #pragma unroll
        for (int j4 = 0; j4 < 4; j4++)
            #pragma unroll
            for (int rr = 0; rr < 2; rr++) {
                int tok = mw*32 + i*16 + (lane >> 2) + rr*8;
                int nl = nw*32 + j4*8 + 2*(lane & 3);
                sbuf[nl*132 + tok]     = acc[i][j4][rr*2+0];
                sbuf[(nl+1)*132 + tok] = acc[i][j4][rr*2+1];
            }
    __syncthreads();
    int row = tid >> 2;
    int n = n0 + row;
    if (n < bRows) {
        float bv = bias[n];
        const float* srcr = sbuf + row*132;
        float* dstr = outF + ((size_t)zb * bRows + n) * LSEQ + tl0;
        int c0 = (tid & 3) * 4;
        #pragma unroll
        for (int q = 0; q < 8; q++) {
            int col = c0 + q*16;
            float4 v = *(const float4*)(srcr + col);
            v.x += bv; v.y += bv; v.z += bv; v.w += bv;
            *(float4*)(dstr + col) = v;
        }
    }
}

// ---------------- weight converts ----------------
__global__ void wsplit3_k(const float* __restrict__ w0, const float* __restrict__ w1,
                          const float* __restrict__ w2,
                          __nv_bfloat16* __restrict__ h0, __nv_bfloat16* __restrict__ l0,
                          __nv_bfloat16* __restrict__ h1, __nv_bfloat16* __restrict__ l1,
                          __nv_bfloat16* __restrict__ h2, __nv_bfloat16* __restrict__ l2)
{
    int seg = blockIdx.y;
    const float* w = seg==0?w0 : seg==1?w1 : w2;
    __nv_bfloat16* h = seg==0?h0 : seg==1?h1 : h2;
    __nv_bfloat16* l = seg==0?l0 : seg==1?l1 : l2;
    int i = blockIdx.x * blockDim.x + threadIdx.x;
    if (i < 65536) { __nv_bfloat16 hh, ll; bf16split(w[i], hh, ll); h[i] = hh; l[i] = ll; }
}
__global__ void wc3f_k(const float* __restrict__ w, __half* __restrict__ o, int n)
{
    int i = blockIdx.x * blockDim.x + threadIdx.x;
    if (i < n) o[i] = __float2half(w[i]);
}

// ---------------- transpose input0 -> token-major fp32 ----------------
__global__ void xposeF_k(const float* __restrict__ in, float* __restrict__ out)
{
    __shared__ float t[32][33];
    int b = blockIdx.z;
    int tok0 = blockIdx.x * 32, ch0 = blockIdx.y * 32;
    int lx = threadIdx.x & 31, ly = threadIdx.x >> 5;
    #pragma unroll
    for (int i = 0; i < 4; i++) {
        int ch = ch0 + ly + i*8;
        t[lx][ly + i*8] = in[((size_t)b*256 + ch)*LSEQ + tok0 + lx];
    }
    __syncthreads();
    #pragma unroll
    for (int i = 0; i < 4; i++) {
        int tok = tok0 + ly + i*8;
        out[((size_t)b*LSEQ + tok)*256 + ch0 + lx] = t[ly + i*8][lx];
    }
}

// ---------------- layernorm -> token-major bf16 hi/lo ----------------
__global__ void ln_k(const float* __restrict__ in0, const float* __restrict__ in1,
                     const float* __restrict__ w0, const float* __restrict__ b0,
                     const float* __restrict__ w1, const float* __restrict__ b1,
                     __nv_bfloat16* __restrict__ s0h, __nv_bfloat16* __restrict__ s0l,
                     __nv_bfloat16* __restrict__ s1h, __nv_bfloat16* __restrict__ s1l)
{
    int which = blockIdx.y;
    const float* in = which ? in1 : in0;
    const float* w  = which ? w1  : w0;
    const float* bb = which ? b1  : b0;
    __nv_bfloat16* oh = which ? s1h : s0h;
    __nv_bfloat16* ol = which ? s1l : s0l;
    int idx = blockIdx.x * blockDim.x + threadIdx.x;
    int b = idx >> 12, l = idx & (LSEQ-1);
    const float* p = in + (size_t)b*DIMC*LSEQ + l;
    float s = 0.f, s2 = 0.f;
    #pragma unroll 8
    for (int c = 0; c < DIMC; c++) { float v = p[(size_t)c*LSEQ]; s += v; s2 += v*v; }
    float mean = s * (1.f/DIMC);
    float var  = s2 * (1.f/DIMC) - mean*mean;
    float rstd = rsqrtf(var + EPS_F);
    size_t ob = (size_t)idx * 256;
    for (int c0 = 0; c0 < DIMC; c0 += 8) {
        __align__(16) __nv_bfloat16 hh[8], ll[8];
        #pragma unroll
        for (int j = 0; j < 8; j++) {
            float v = (p[(size_t)(c0+j)*LSEQ] - mean) * rstd * w[c0+j] + bb[c0+j];
            bf16split(v, hh[j], ll[j]);
        }
        *(uint4*)(oh + ob + c0) = *(uint4*)hh;
        *(uint4*)(ol + ob + c0) = *(uint4*)ll;
    }
}

// ---------------- depthwise causal conv (K=4) + silu — both dirs ----------------
__global__ void conv_silu_k(const float* __restrict__ x,
                            const float* __restrict__ wf, const float* __restrict__ bf,
                            const float* __restrict__ wb, const float* __restrict__ bbias,
                            float* __restrict__ xc)
{
    int t   = blockIdx.x * blockDim.x + threadIdx.x;
    int bdd = blockIdx.y;
    int dir = bdd >> 9;
    int bd  = bdd & 511;
    int d   = bd & 255;
    const float* w  = dir ? wb : wf;
    const float* bi = dir ? bbias : bf;
    const float* xp = x + (size_t)bd*LSEQ;
    float acc = bi[d];
    #pragma unroll
    for (int k = 0; k < 4; k++) {
        int s = t - 3 + k;
        if (s >= 0) {
            int ph = dir ? (LSEQ-1-s) : s;
            acc += w[d*4+k] * xp[ph];
        }
    }
    xc[(size_t)bdd*LSEQ + t] = acc * sigmoidf_(acc);
}

// ---------------- fp32 SGEMM (xproj / dtproj), per-dir weight select ----------------
enum { EP_NONE=0, EP_SPBIAS=1 };

template<int EP>
__global__ void __launch_bounds__(256) sgemm_k(
    const float* __restrict__ A0, const float* __restrict__ A1, int lda,
    const float* __restrict__ B, int ldb, long long bStride,
    float* __restrict__ C, int ldc, long long cStride,
    int M, int Kdim,
    const float* __restrict__ bias0, const float* __restrict__ bias1)
{
    __shared__ float As[8][128];
    __shared__ float Bs[8][128];
    int zb = blockIdx.z;
    int dir = zb >> 1;
    const float* A = dir ? A1 : A0;
    const float* bias = dir ? bias1 : bias0;
    B += (size_t)zb * bStride;
    C += (size_t)zb * cStride;

    int m0 = blockIdx.y * 128;
    int n0 = blockIdx.x * 128;
    int tid = threadIdx.x;
    int ar  = tid >> 1, ac = (tid & 1) << 2;
    int brr = tid >> 5, bc = (tid & 31) << 2;
    int mt0 = (tid >> 4) << 2, nt0 = (tid & 15) << 2;

    unsigned long long acc[8][4];
    #pragma unroll
    for (int i = 0; i < 8; i++)
        #pragma unroll
        for (int j = 0; j < 4; j++) acc[i][j] = 0ull;

    for (int k0 = 0; k0 < Kdim; k0 += 8) {
        float4 a4 = make_float4(0.f,0.f,0.f,0.f);
        int arow = m0 + ar;
        if (arow < M) a4 = *(const float4*)(A + (size_t)arow*lda + (k0 + ac));
        As[ac+0][ar] = a4.x; As[ac+1][ar] = a4.y; As[ac+2][ar] = a4.z; As[ac+3][ar] = a4.w;
        float4 b4 = *(const float4*)(B + (size_t)(k0 + brr)*ldb + (n0 + bc));
        *(float4*)&Bs[brr][bc] = b4;
        __syncthreads();
        #pragma unroll
        for (int kk = 0; kk < 8; kk++) {
            float4 aL = *(const float4*)&As[kk][mt0];
            float4 aH = *(const float4*)&As[kk][mt0+64];
            float av[8] = {aL.x,aL.y,aL.z,aL.w,aH.x,aH.y,aH.z,aH.w};
            unsigned long long b2[4];
            const unsigned long long* bpL = (const unsigned long long*)&Bs[kk][nt0];
            const unsigned long long* bpH = (const unsigned long long*)&Bs[kk][nt0+64];
            b2[0] = bpL[0]; b2[1] = bpL[1]; b2[2] = bpH[0]; b2[3] = bpH[1];
            #pragma unroll
            for (int i = 0; i < 8; i++) {
                unsigned long long a2;
                asm("mov.b64 %0, {%1, %1};" : "=l"(a2) : "f"(av[i]));
                #pragma unroll
                for (int j = 0; j < 4; j++)
                    asm("fma.rn.f32x2 %0, %1, %2, %0;" : "+l"(acc[i][j]) : "l"(a2), "l"(b2[j]));
            }
        }
        __syncthreads();
    }

    #pragma unroll
    for (int i = 0; i < 8; i++) {
        int m = m0 + ((i < 4) ? (mt0 + i) : (64 + mt0 + i - 4));
        if (m >= M) continue;
        float bv = (EP == EP_SPBIAS) ? bias[m] : 0.f;
        #pragma unroll
        for (int j = 0; j < 4; j++) {
            int n = n0 + ((j < 2) ? (nt0 + 2*j) : (64 + nt0 + 2*(j-2)));
            float2 v;
            asm("mov.b64 {%0, %1}, %2;" : "=f"(v.x), "=f"(v.y) : "l"(acc[i][j]));
            if (EP == EP_SPBIAS) { v.x = softplusf_(v.x + bv); v.y = softplusf_(v.y + bv); }
            *(float2*)(C + (size_t)m*ldc + n) = v;
        }
    }
}

// ---------------- chunked selective scan (both dirs in one launch) ----------------
__global__ void __launch_bounds__(256) scanA_k(
    const float* __restrict__ dt, const float* __restrict__ xc,
    const float* __restrict__ dbl,
    const float* __restrict__ A0, const float* __restrict__ A1,
    float* __restrict__ P, float* __restrict__ S)
{
    __shared__ float sdt[32][65], sx[32][65], sB[8][65];
    int chunk = blockIdx.x, zd = blockIdx.y, d0 = blockIdx.z * 32;
    int dir = zd >> 1, b = zd & 1;
    const float* Alog = dir ? A1 : A0;
    int tid = threadIdx.x;
    size_t base = ((size_t)(zd*DIMC + d0))*LSEQ + chunk*64;
    for (int i = tid; i < 2048; i += 256) {
        int r = i >> 6, c = i & 63;
        sdt[r][c] = dt[base + (size_t)r*LSEQ + c];
        sx [r][c] = xc[base + (size_t)r*LSEQ + c];
    }
    size_t bbase = ((size_t)(zd*32 + 16))*LSEQ + chunk*64;
    for (int i = tid; i < 512; i += 256) {
        int r = i >> 6, c = i & 63;
        sB[r][c] = dbl[bbase + (size_t)r*LSEQ + c];
    }
    __syncthreads();
    int dl = tid >> 3, n = tid & 7;
    float Aa = -__expf(Alog[(d0+dl)*8 + n]);
    float Pv = 1.f, Sv = 0.f;
    #pragma unroll 8
    for (int t = 0; t < 64; t++) {
        float dtv = sdt[dl][t];
        float dA  = __expf(dtv * Aa);
        Sv = Sv*dA + dtv * sx[dl][t] * sB[n][t];
        Pv *= dA;
    }
    size_t o = (size_t)dir*SCN_ + (((size_t)chunk*BATCH + b)*DIMC + d0+dl)*8 + n;
    P[o] = Pv; S[o] = Sv;
}

__global__ void scanB_k(const float* __restrict__ P, const float* __restrict__ S,
                        float* __restrict__ Hi)
{
    int gid = blockIdx.x * blockDim.x + threadIdx.x;
    int dir = gid >> 12, idx = gid & 4095;
    const float* Pd = P + (size_t)dir*SCN_;
    const float* Sd = S + (size_t)dir*SCN_;
    float* Hd = Hi + (size_t)dir*SCN_;
    float h = 0.f;
    for (int c0 = 0; c0 < 64; c0 += 8) {
        float p[8], s[8];
        #pragma unroll
        for (int j = 0; j < 8; j++) {
            size_t o = (size_t)(c0+j)*4096 + idx;
            p[j] = Pd[o]; s[j] = Sd[o];
        }
        #pragma unroll
        for (int j = 0; j < 8; j++) {
            Hd[(size_t)(c0+j)*4096 + idx] = h;
            h = h * p[j] + s[j];
        }
    }
}

__global__ void __launch_bounds__(256) scanC_k(
    const float* __restrict__ dt, const float* __restrict__ xc,
    const float* __restrict__ dbl,
    const float* __restrict__ A0, const float* __restrict__ A1,
    const float* __restrict__ Hi,
    const float* __restrict__ D0, const float* __restrict__ D1,
    const float* __restrict__ z, float* __restrict__ y)
{
    __shared__ float sdt[32][65], sx[32][65], sB[8][65], sC[8][65];
    __shared__ float sy[32][64];
    int chunk = blockIdx.x, zd = blockIdx.y, d0 = blockIdx.z * 32;
    int dir = zd >> 1, b = zd & 1;
    const float* Alog = dir ? A1 : A0;
    const float* Dp   = dir ? D1 : D0;
    int tid = threadIdx.x;
    size_t base = ((size_t)(zd*DIMC + d0))*LSEQ + chunk*64;
    for (int i = tid; i < 2048; i += 256) {
        int r = i >> 6, c = i & 63;
        sdt[r][c] = dt[base + (size_t)r*LSEQ + c];
        sx [r][c] = xc[base + (size_t)r*LSEQ + c];
    }
    size_t bbase = ((size_t)(zd*32 + 16))*LSEQ + chunk*64;
    size_t cbase = ((size_t)(zd*32 + 24))*LSEQ + chunk*64;
    for (int i = tid; i < 512; i += 256) {
        int r = i >> 6, c = i & 63;
        sB[r][c] = dbl[bbase + (size_t)r*LSEQ + c];
        sC[r][c] = dbl[cbase + (size_t)r*LSEQ + c];
    }
    __syncthreads();
    int dl = tid >> 3, n = tid & 7;
    float Aa = -__expf(Alog[(d0+dl)*8 + n]);
    float h = Hi[(size_t)dir*SCN_ + (((size_t)chunk*BATCH + b)*DIMC + d0+dl)*8 + n];
    for (int t = 0; t < 64; t++) {
        float dtv = sdt[dl][t];
        float dA  = __expf(dtv * Aa);
        h = h*dA + dtv * sx[dl][t] * sB[n][t];
        float yv = h * sC[n][t];
        yv += __shfl_down_sync(0xffffffffu, yv, 4);
        yv += __shfl_down_sync(0xffffffffu, yv, 2);
        yv += __shfl_down_sync(0xffffffffu, yv, 1);
        if (n == 0) sy[dl][t] = yv;
    }
    __syncthreads();
    float* yD = y + (size_t)dir * BATCH*DIMC*LSEQ;
    for (int i = tid; i < 2048; i += 256) {
        int r = i >> 6, c = i & 63;
        int tl = chunk*64 + c;
        int lp = dir ? (LSEQ-1-tl) : tl;
        size_t gi = ((size_t)(b*DIMC + d0 + r))*LSEQ + lp;
        float v = sy[r][c] + sx[r][c]*Dp[d0+r];
        float zz = z[gi];
        yD[gi] = v * zz * sigmoidf_(zz);
    }
}

// ---------------- rmsnorm 3 heads -> token-major bf16 hi/lo ----------------
__global__ void rms3_k(const float* __restrict__ yf, const float* __restrict__ yb,
                       const float* __restrict__ w,
                       __nv_bfloat16* __restrict__ ynh, __nv_bfloat16* __restrict__ ynl)
{
    int idx = blockIdx.x * blockDim.x + threadIdx.x;
    int b = idx >> 12, l = idx & (LSEQ-1);
    size_t base = (size_t)b*DIMC*LSEQ + l;
    float sa = 0.f, sf = 0.f, sb = 0.f;
    #pragma unroll 8
    for (int d = 0; d < DIMC; d++) {
        float vf = yf[base + (size_t)d*LSEQ];
        float vb = yb[base + (size_t)d*LSEQ];
        float va = 0.5f*(vf+vb);
        sa += va*va; sf += vf*vf; sb += vb*vb;
    }
    float ra = rsqrtf(sa*(1.f/DIMC) + EPS_F);
    float rf = rsqrtf(sf*(1.f/DIMC) + EPS_F);
    float rb = rsqrtf(sb*(1.f/DIMC) + EPS_F);
    size_t r0 = ((size_t)(0*2 + b)*LSEQ + l) * 256;
    size_t r1 = ((size_t)(1*2 + b)*LSEQ + l) * 256;
    size_t r2 = ((size_t)(2*2 + b)*LSEQ + l) * 256;
    for (int d0 = 0; d0 < DIMC; d0 += 8) {
        __align__(16) __nv_bfloat16 h0[8], l0[8], h1[8], l1[8], h2[8], l2[8];
        #pragma unroll
        for (int j = 0; j < 8; j++) {
            int d = d0 + j;
            float vf = yf[base + (size_t)d*LSEQ];
            float vb = yb[base + (size_t)d*LSEQ];
            float va = 0.5f*(vf+vb);
            float ww = w[d];
            bf16split(va*ra*ww, h0[j], l0[j]);
            bf16split(vf*rf*ww, h1[j], l1[j]);
            bf16split(vb*rb*ww, h2[j], l2[j]);
        }
        *(uint4*)(ynh + r0 + d0) = *(uint4*)h0; *(uint4*)(ynl + r0 + d0) = *(uint4*)l0;
        *(uint4*)(ynh + r1 + d0) = *(uint4*)h1; *(uint4*)(ynl + r1 + d0) = *(uint4*)l1;
        *(uint4*)(ynh + r2 + d0) = *(uint4*)h2; *(uint4*)(ynl + r2 + d0) = *(uint4*)l2;
    }
}

// ---------------- launch ----------------
extern "C" void kernel_launch(void* const* d_in, const int* in_sizes, int n_in,
                              void* d_out, int out_size)
{
    (void)in_sizes; (void)n_in; (void)out_size;
    const float* input0      = (const float*)d_in[0];
    const float* input1      = (const float*)d_in[1];
    const float* norm0_w     = (const float*)d_in[2];
    const float* norm0_b     = (const float*)d_in[3];
    const float* norm1_w     = (const float*)d_in[4];
    const float* norm1_b     = (const float*)d_in[5];
    const float* in_proj_w   = (const float*)d_in[6];
    const float* in_projz_w  = (const float*)d_in[7];
    const float* conv1d_w    = (const float*)d_in[8];
    const float* conv1d_bias = (const float*)d_in[9];
    const float* conv1db_w   = (const float*)d_in[10];
    const float* conv1db_bias= (const float*)d_in[11];
    const float* xproj_w     = (const float*)d_in[12];
    const float* xprojb_w    = (const float*)d_in[13];
    const float* dtproj_w    = (const float*)d_in[14];
    const float* dtproj_bias = (const float*)d_in[15];
    const float* dtprojb_w   = (const float*)d_in[16];
    const float* dtprojb_bias= (const float*)d_in[17];
    const float* A_log       = (const float*)d_in[18];
    const float* Ab_log      = (const float*)d_in[19];
    const float* D_p         = (const float*)d_in[20];
    const float* D_b         = (const float*)d_in[21];
    const float* rms_w       = (const float*)d_in[22];
    const float* out_proj_w  = (const float*)d_in[23];
    const float* conv3d_w    = (const float*)d_in[24];
    const float* conv3d_bias = (const float*)d_in[25];
    float* out = (float*)d_out;

    float *x_, *z_, *xc_, *dbl_, *dt_, *P_, *S_, *Hi_, *y_, *skipT;
    __nv_bfloat16 *s0h,*s0l,*s1h,*s1l,*ynh,*ynl;
    __half *of_, *wc3f;
    __nv_bfloat16 *wip_h,*wip_l,*wiz_h,*wiz_l,*wop_h,*wop_l;
    cudaGetSymbolAddress((void**)&x_,   g_x);
    cudaGetSymbolAddress((void**)&z_,   g_z);
    cudaGetSymbolAddress((void**)&xc_,  g_xc);
    cudaGetSymbolAddress((void**)&dbl_, g_dbl);
    cudaGetSymbolAddress((void**)&dt_,  g_dt);
    cudaGetSymbolAddress((void**)&P_,   g_P);
    cudaGetSymbolAddress((void**)&S_,   g_S);
    cudaGetSymbolAddress((void**)&Hi_,  g_Hi);
    cudaGetSymbolAddress((void**)&y_,   g_y);
    cudaGetSymbolAddress((void**)&skipT,g_skipT);
    cudaGetSymbolAddress((void**)&s0h,  g_s0h);
    cudaGetSymbolAddress((void**)&s0l,  g_s0l);
    cudaGetSymbolAddress((void**)&s1h,  g_s1h);
    cudaGetSymbolAddress((void**)&s1l,  g_s1l);
    cudaGetSymbolAddress((void**)&ynh,  g_ynh);
    cudaGetSymbolAddress((void**)&ynl,  g_ynl);
    cudaGetSymbolAddress((void**)&of_,  g_of);
    cudaGetSymbolAddress((void**)&wc3f, g_wc3f);
    cudaGetSymbolAddress((void**)&wip_h, g_wip_h); cudaGetSymbolAddress((void**)&wip_l, g_wip_l);
    cudaGetSymbolAddress((void**)&wiz_h, g_wiz_h); cudaGetSymbolAddress((void**)&wiz_l, g_wiz_l);
    cudaGetSymbolAddress((void**)&wop_h, g_wop_h); cudaGetSymbolAddress((void**)&wop_l, g_wop_l);

    const int TCSMEM  = 2 * STG;    // 110592
    const int TCSMEMH = 2 * STGH;   // 55296
    cudaFuncSetAttribute(tcgemm_k<EPT_XPOSE>, cudaFuncAttributeMaxDynamicSharedMemorySize, TCSMEM);
    cudaFuncSetAttribute(tcgemm_k<EPT_SKIP>,  cudaFuncAttributeMaxDynamicSharedMemorySize, TCSMEM);
    cudaFuncSetAttribute(tcgemmH_k,           cudaFuncAttributeMaxDynamicSharedMemorySize, TCSMEMH);

    const long long SB  = (long long)DIMC*LSEQ;
    const long long SB32= (long long)32*LSEQ;

    // 0) weight converts + skip transpose
    wsplit3_k<<<dim3(256,3), 256>>>(in_proj_w, in_projz_w, out_proj_w,
                                    wip_h, wip_l, wiz_h, wiz_l, wop_h, wop_l);
    wc3f_k<<<1200, 256>>>(conv3d_w, wc3f, 307200);
    xposeF_k<<<dim3(128,8,2), 256>>>(input0, skipT);

    // 1) layernorms -> token-major bf16 hi/lo
    ln_k<<<dim3(32,2), 256>>>(input0, input1, norm0_w, norm0_b, norm1_w, norm1_b,
                              s0h, s0l, s1h, s1l);

    // 2) in_proj / in_projz (3-pass bf16) -> channel-major fp32
    tcgemm_k<EPT_XPOSE><<<dim3(4,32,2), 256, TCSMEM>>>(s0h, s0l, wip_h, wip_l, 256,
                                                       x_, nullptr, nullptr);
    tcgemm_k<EPT_XPOSE><<<dim3(4,32,2), 256, TCSMEM>>>(s1h, s1l, wiz_h, wiz_l, 256,
                                                       z_, nullptr, nullptr);

    // 3) conv + silu, both dirs
    conv_silu_k<<<dim3(16,1024), 256>>>(x_, conv1d_w, conv1d_bias, conv1db_w, conv1db_bias,
                                        (float*)xc_);
    // 4) xproj, both dirs
    sgemm_k<EP_NONE><<<dim3(32,1,4), 256>>>(xproj_w, xprojb_w, 256,
                                            xc_, LSEQ, SB, dbl_, LSEQ, SB32,
                                            32, 256, nullptr, nullptr);
    // 5) dtproj + softplus, both dirs
    sgemm_k<EP_SPBIAS><<<dim3(32,2,4), 256>>>(dtproj_w, dtprojb_w, 16,
                                              dbl_, LSEQ, SB32, dt_, LSEQ, SB,
                                              256, 16, dtproj_bias, dtprojb_bias);
    // 6) chunked scan, both dirs
    scanA_k<<<dim3(64,4,8), 256>>>(dt_, xc_, dbl_, A_log, Ab_log, P_, S_);
    scanB_k<<<32, 256>>>(P_, S_, Hi_);
    scanC_k<<<dim3(64,4,8), 256>>>(dt_, xc_, dbl_, A_log, Ab_log, Hi_, D_p, D_b, z_, y_);

    // 7) rmsnorm 3 heads
    rms3_k<<<32, 256>>>(y_, y_ + (size_t)BATCH*DIMC*LSEQ, rms_w, ynh, ynl);

    // 8) out_proj (+skip) (3-pass bf16) -> token-major fp16 o
    tcgemm_k<EPT_SKIP><<<dim3(4,32,6), 256, TCSMEM>>>(ynh, ynl, wop_h, wop_l, 256,
                                                      nullptr, skipT, of_);

    // 9) conv3d (1-pass fp16, +bias) -> final output (channel-major fp32)
    tcgemmH_k<<<dim3(19,32,6), 256, TCSMEMH>>>(of_, wc3f, 1200, out, conv3d_bias);
}

// round 14
// speedup vs baseline: 1.9059x; 1.9059x over previous
#include <cuda_runtime.h>
#include <cuda_bf16.h>
#include <cuda_fp16.h>
#include <cstdint>
#include <math.h>

#define LSEQ 4096
#define BATCH 2
#define DIMC 256
#define EPS_F 1e-5f
#define SCN_ (64*BATCH*DIMC*8)

// ---------------- scratch (device globals) ----------------
__device__ float g_x   [BATCH*DIMC*LSEQ];
__device__ float g_z   [BATCH*DIMC*LSEQ];
__device__ float g_xc  [2][BATCH*DIMC*LSEQ];
__device__ float g_dbl [2][BATCH*32*LSEQ];
__device__ float g_dt  [2][BATCH*DIMC*LSEQ];
__device__ float g_P   [2][SCN_];
__device__ float g_S   [2][SCN_];
__device__ float g_Hi  [2][SCN_];
__device__ float g_y   [2][BATCH*DIMC*LSEQ];
__device__ float g_skipT[BATCH*LSEQ*DIMC];

__device__ __nv_bfloat16 g_s0h[BATCH*LSEQ*DIMC], g_s0l[BATCH*LSEQ*DIMC];
__device__ __nv_bfloat16 g_s1h[BATCH*LSEQ*DIMC], g_s1l[BATCH*LSEQ*DIMC];
__device__ __nv_bfloat16 g_ynh[6*LSEQ*DIMC],     g_ynl[6*LSEQ*DIMC];
__device__ __half        g_of [6*LSEQ*DIMC];
__device__ __nv_bfloat16 g_wip_h[DIMC*DIMC], g_wip_l[DIMC*DIMC];
__device__ __nv_bfloat16 g_wiz_h[DIMC*DIMC], g_wiz_l[DIMC*DIMC];
__device__ __nv_bfloat16 g_wop_h[DIMC*DIMC], g_wop_l[DIMC*DIMC];
__device__ __half        g_wc3f[1200*DIMC];

__device__ __forceinline__ float sigmoidf_(float x){ return 1.f/(1.f+__expf(-x)); }
__device__ __forceinline__ float softplusf_(float x){ return x>20.f ? x : log1pf(__expf(x)); }

__device__ __forceinline__ void bf16split(float v, __nv_bfloat16& h, __nv_bfloat16& l) {
    h = __float2bfloat16(v);
    l = __float2bfloat16(v - __bfloat162float(h));
}
__device__ __forceinline__ uint32_t packsplit(float v) {
    __nv_bfloat16 h, l; bf16split(v, h, l);
    return (uint32_t)__bfloat16_as_ushort(h) | ((uint32_t)__bfloat16_as_ushort(l) << 16);
}

__device__ __forceinline__ uint32_t smem_u32(const void* p) {
    uint32_t a;
    asm("{ .reg .u64 t; cvta.to.shared.u64 t, %1; cvt.u32.u64 %0, t; }" : "=r"(a) : "l"(p));
    return a;
}
__device__ __forceinline__ void ldmx4(uint32_t* r, uint32_t addr) {
    asm volatile("ldmatrix.sync.aligned.m8n8.x4.shared.b16 {%0,%1,%2,%3}, [%4];"
        : "=r"(r[0]),"=r"(r[1]),"=r"(r[2]),"=r"(r[3]) : "r"(addr));
}
__device__ __forceinline__ void mma16816(float* d, const uint32_t* a, uint32_t b0, uint32_t b1) {
    asm volatile("mma.sync.aligned.m16n8k16.row.col.f32.bf16.bf16.f32 "
        "{%0,%1,%2,%3}, {%4,%5,%6,%7}, {%8,%9}, {%0,%1,%2,%3};"
        : "+f"(d[0]),"+f"(d[1]),"+f"(d[2]),"+f"(d[3])
        : "r"(a[0]),"r"(a[1]),"r"(a[2]),"r"(a[3]), "r"(b0),"r"(b1));
}
__device__ __forceinline__ void mma16816h(float* d, const uint32_t* a, uint32_t b0, uint32_t b1) {
    asm volatile("mma.sync.aligned.m16n8k16.row.col.f32.f16.f16.f32 "
        "{%0,%1,%2,%3}, {%4,%5,%6,%7}, {%8,%9}, {%0,%1,%2,%3};"
        : "+f"(d[0]),"+f"(d[1]),"+f"(d[2]),"+f"(d[3])
        : "r"(a[0]),"r"(a[1]),"r"(a[2]),"r"(a[3]), "r"(b0),"r"(b1));
}
__device__ __forceinline__ void cp16(uint32_t dst, const void* src, int sz) {
    asm volatile("cp.async.cg.shared.global [%0], [%1], 16, %2;"
        :: "r"(dst), "l"(__cvta_generic_to_global(src)), "r"(sz) : "memory");
}

// ---------------- split-bf16 GEMM (3-pass), cp.async double-buffered, 128x64 ----------------
#define EPT_XPOSE 0
#define EPT_SKIP  1
#define TILE_A  18432
#define TILE_BB 9216
#define STG     (2*TILE_A + 2*TILE_BB)   // 55296

template<int EPT>
__global__ void __launch_bounds__(256, 2) tcgemm_k(
    const __nv_bfloat16* __restrict__ Ah, const __nv_bfloat16* __restrict__ Al,
    const __nv_bfloat16* __restrict__ Bh, const __nv_bfloat16* __restrict__ Bl,
    int bRows,
    float* __restrict__ outF,
    const float* __restrict__ skipT,
    __half* __restrict__ Of)
{
    extern __shared__ char smem[];
    const int tid = threadIdx.x, lane = tid & 31, warp = tid >> 5;
    const int mw = warp & 3, nw = warp >> 2;
    const int n0 = blockIdx.x * 64, tl0 = blockIdx.y * 128, zb = blockIdx.z;
    const long long t0 = (long long)zb * LSEQ + tl0;

    float acc[2][4][4];
    #pragma unroll
    for (int i = 0; i < 2; i++)
        #pragma unroll
        for (int j = 0; j < 4; j++)
            #pragma unroll
            for (int c = 0; c < 4; c++) acc[i][j][c] = 0.f;

    const uint32_t sbase = smem_u32(smem);
    const int a_row  = (lane & 7) + ((lane >> 3) & 1) * 8;
    const int a_kadd = (lane >> 4) * 8;
    const int b_row  = (lane & 7) + (lane >> 4) * 8;
    const int b_kadd = ((lane >> 3) & 1) * 8;
    const uint32_t aoffH = sbase + 0        + (uint32_t)((mw*32 + a_row)*72 + a_kadd) * 2;
    const uint32_t boffH = sbase + 2*TILE_A + (uint32_t)((nw*32 + b_row)*72 + b_kadd) * 2;

    const int lrow = tid >> 3, lc8 = (tid & 7) * 8;

    auto load_chunk = [&](int kc, int stage) {
        const int kofs = kc * 64;
        const uint32_t sb0 = sbase + stage * STG;
        #pragma unroll
        for (int it = 0; it < 4; it++) {
            int row = lrow + it * 32;
            uint32_t sa = sb0 + (uint32_t)(row * 72 + lc8) * 2;
            cp16(sa,          Ah + (t0 + row) * 256 + kofs + lc8, 16);
            cp16(sa + TILE_A, Al + (t0 + row) * 256 + kofs + lc8, 16);
        }
        #pragma unroll
        for (int it = 0; it < 2; it++) {
            int row = lrow + it * 32;
            uint32_t sa = sb0 + 2*TILE_A + (uint32_t)(row * 72 + lc8) * 2;
            int brow = n0 + row;
            int ok = (brow < bRows) ? 16 : 0;
            if (brow >= bRows) brow = bRows - 1;
            cp16(sa,           Bh + (size_t)brow * 256 + kofs + lc8, ok);
            cp16(sa + TILE_BB, Bl + (size_t)brow * 256 + kofs + lc8, ok);
        }
    };

    auto compute = [&](int stage) {
        const uint32_t sadd = (uint32_t)stage * STG;
        #pragma unroll
        for (int ks = 0; ks < 4; ks++) {
            const uint32_t k2 = (uint32_t)(ks * 16) * 2;
            uint32_t aH[2][4], aL[2][4];
            #pragma unroll
            for (int i = 0; i < 2; i++) {
                ldmx4(aH[i], aoffH + sadd + i*16*144 + k2);
                ldmx4(aL[i], aoffH + sadd + TILE_A + i*16*144 + k2);
            }
            uint32_t bH[2][4], bL[2][4];
            #pragma unroll
            for (int g = 0; g < 2; g++) {
                ldmx4(bH[g], boffH + sadd + g*16*144 + k2);
                ldmx4(bL[g], boffH + sadd + TILE_BB + g*16*144 + k2);
            }
            #pragma unroll
            for (int i = 0; i < 2; i++)
                #pragma unroll
                for (int g = 0; g < 2; g++)
                    #pragma unroll
                    for (int p = 0; p < 2; p++) {
                        int j4 = g*2 + p;
                        mma16816(acc[i][j4], aH[i], bH[g][2*p], bH[g][2*p+1]);
                        mma16816(acc[i][j4], aH[i], bL[g][2*p], bL[g][2*p+1]);
                        mma16816(acc[i][j4], aL[i], bH[g][2*p], bH[g][2*p+1]);
                    }
        }
    };

    load_chunk(0, 0);
    asm volatile("cp.async.commit_group;" ::: "memory");
    for (int kc = 0; kc < 4; kc++) {
        if (kc < 3) {
            load_chunk(kc + 1, (kc + 1) & 1);
            asm volatile("cp.async.commit_group;" ::: "memory");
            asm volatile("cp.async.wait_group 1;" ::: "memory");
        } else {
            asm volatile("cp.async.wait_group 0;" ::: "memory");
        }
        __syncthreads();
        compute(kc & 1);
        __syncthreads();
    }

    if (EPT == EPT_SKIP) {
        #pragma unroll
        for (int i = 0; i < 2; i++)
            #pragma unroll
            for (int rr = 0; rr < 2; rr++) {
                int tok = tl0 + mw*32 + i*16 + (lane >> 2) + rr*8;
                size_t orow = ((size_t)zb * LSEQ + tok) * 256;
                size_t srow = ((size_t)(zb & 1) * LSEQ + tok) * 256;
                #pragma unroll
                for (int j4 = 0; j4 < 4; j4++) {
                    int n = n0 + nw*32 + j4*8 + 2*(lane & 3);
                    float2 sk = *(const float2*)(skipT + srow + n);
                    __half2 hv;
                    hv.x = __float2half(acc[i][j4][rr*2+0] + sk.x);
                    hv.y = __float2half(acc[i][j4][rr*2+1] + sk.y);
                    *(__half2*)(Of + orow + n) = hv;
                }
            }
    } else {
        float* sbuf = (float*)smem;
        __syncthreads();
        #pragma unroll
        for (int i = 0; i < 2; i++)
            #pragma unroll
            for (int j4 = 0; j4 < 4; j4++)
                #pragma unroll
                for (int rr = 0; rr < 2; rr++) {
                    int tok = mw*32 + i*16 + (lane >> 2) + rr*8;
                    int nl = nw*32 + j4*8 + 2*(lane & 3);
                    sbuf[nl*132 + tok]     = acc[i][j4][rr*2+0];
                    sbuf[(nl+1)*132 + tok] = acc[i][j4][rr*2+1];
                }
        __syncthreads();
        int row = tid >> 2;
        int n = n0 + row;
        if (n < bRows) {
            const float* srcr = sbuf + row*132;
            float* dstr = outF + ((size_t)zb * bRows + n) * LSEQ + tl0;
            int c0 = (tid & 3) * 4;
            #pragma unroll
            for (int q = 0; q < 8; q++) {
                int col = c0 + q*16;
                *(float4*)(dstr + col) = *(const float4*)(srcr + col);
            }
        }
    }
}

// ---------------- single-pass fp16 GEMM (conv3d), cp.async double-buffered ----------------
#define STGH (TILE_A + TILE_BB)   // 27648

__global__ void __launch_bounds__(256, 2) tcgemmH_k(
    const __half* __restrict__ A, const __half* __restrict__ W, int bRows,
    float* __restrict__ outF, const float* __restrict__ bias)
{
    extern __shared__ char smem[];
    const int tid = threadIdx.x, lane = tid & 31, warp = tid >> 5;
    const int mw = warp & 3, nw = warp >> 2;
    const int n0 = blockIdx.x * 64, tl0 = blockIdx.y * 128, zb = blockIdx.z;
    const long long t0 = (long long)zb * LSEQ + tl0;

    float acc[2][4][4];
    #pragma unroll
    for (int i = 0; i < 2; i++)
        #pragma unroll
        for (int j = 0; j < 4; j++)
            #pragma unroll
            for (int c = 0; c < 4; c++) acc[i][j][c] = 0.f;

    const uint32_t sbase = smem_u32(smem);
    const int a_row  = (lane & 7) + ((lane >> 3) & 1) * 8;
    const int a_kadd = (lane >> 4) * 8;
    const int b_row  = (lane & 7) + (lane >> 4) * 8;
    const int b_kadd = ((lane >> 3) & 1) * 8;
    const uint32_t aoff = sbase + 0      + (uint32_t)((mw*32 + a_row)*72 + a_kadd) * 2;
    const uint32_t boff = sbase + TILE_A + (uint32_t)((nw*32 + b_row)*72 + b_kadd) * 2;

    const int lrow = tid >> 3, lc8 = (tid & 7) * 8;

    auto load_chunk = [&](int kc, int stage) {
        const int kofs = kc * 64;
        const uint32_t sb0 = sbase + stage * STGH;
        #pragma unroll
        for (int it = 0; it < 4; it++) {
            int row = lrow + it * 32;
            cp16(sb0 + (uint32_t)(row * 72 + lc8) * 2, A + (t0 + row) * 256 + kofs + lc8, 16);
        }
        #pragma unroll
        for (int it = 0; it < 2; it++) {
            int row = lrow + it * 32;
            int brow = n0 + row;
            int ok = (brow < bRows) ? 16 : 0;
            if (brow >= bRows) brow = bRows - 1;
            cp16(sb0 + TILE_A + (uint32_t)(row * 72 + lc8) * 2,
                 W + (size_t)brow * 256 + kofs + lc8, ok);
        }
    };

    auto compute = [&](int stage) {
        const uint32_t sadd = (uint32_t)stage * STGH;
        #pragma unroll
        for (int ks = 0; ks < 4; ks++) {
            const uint32_t k2 = (uint32_t)(ks * 16) * 2;
            uint32_t aF[2][4], bF[2][4];
            #pragma unroll
            for (int i = 0; i < 2; i++) ldmx4(aF[i], aoff + sadd + i*16*144 + k2);
            #pragma unroll
            for (int g = 0; g < 2; g++) ldmx4(bF[g], boff + sadd + g*16*144 + k2);
            #pragma unroll
            for (int i = 0; i < 2; i++)
                #pragma unroll
                for (int g = 0; g < 2; g++)
                    #pragma unroll
                    for (int p = 0; p < 2; p++)
                        mma16816h(acc[i][g*2+p], aF[i], bF[g][2*p], bF[g][2*p+1]);
        }
    };

    load_chunk(0, 0);
    asm volatile("cp.async.commit_group;" ::: "memory");
    for (int kc = 0; kc < 4; kc++) {
        if (kc < 3) {
            load_chunk(kc + 1, (kc + 1) & 1);
            asm volatile("cp.async.commit_group;" ::: "memory");
            asm volatile("cp.async.wait_group 1;" ::: "memory");
        } else {
            asm volatile("cp.async.wait_group 0;" ::: "memory");
        }
        __syncthreads();
        compute(kc & 1);
        __syncthreads();
    }

    float* sbuf = (float*)smem;
    __syncthreads();
    #pragma unroll
    for (int i = 0; i < 2; i++)
        #pragma unroll
        for (int j4 = 0; j4 < 4; j4++)
            #pragma unroll
            for (int rr = 0; rr < 2; rr++) {
                int tok = mw*32 + i*16 + (lane >> 2) + rr*8;
                int nl = nw*32 + j4*8 + 2*(lane & 3);
                sbuf[nl*132 + tok]     = acc[i][j4][rr*2+0];
                sbuf[(nl+1)*132 + tok] = acc[i][j4][rr*2+1];
            }
    __syncthreads();
    int row = tid >> 2;
    int n = n0 + row;
    if (n < bRows) {
        float bv = bias[n];
        const float* srcr = sbuf + row*132;
        float* dstr = outF + ((size_t)zb * bRows + n) * LSEQ + tl0;
        int c0 = (tid & 3) * 4;
        #pragma unroll
        for (int q = 0; q < 8; q++) {
            int col = c0 + q*16;
            float4 v = *(const float4*)(srcr + col);
            v.x += bv; v.y += bv; v.z += bv; v.w += bv;
            *(float4*)(dstr + col) = v;
        }
    }
}

// ---------------- weight converts ----------------
__global__ void wsplit3_k(const float* __restrict__ w0, const float* __restrict__ w1,
                          const float* __restrict__ w2,
                          __nv_bfloat16* __restrict__ h0, __nv_bfloat16* __restrict__ l0,
                          __nv_bfloat16* __restrict__ h1, __nv_bfloat16* __restrict__ l1,
                          __nv_bfloat16* __restrict__ h2, __nv_bfloat16* __restrict__ l2)
{
    int seg = blockIdx.y;
    const float* w = seg==0?w0 : seg==1?w1 : w2;
    __nv_bfloat16* h = seg==0?h0 : seg==1?h1 : h2;
    __nv_bfloat16* l = seg==0?l0 : seg==1?l1 : l2;
    int i = blockIdx.x * blockDim.x + threadIdx.x;
    if (i < 65536) { __nv_bfloat16 hh, ll; bf16split(w[i], hh, ll); h[i] = hh; l[i] = ll; }
}
__global__ void wc3f_k(const float* __restrict__ w, __half* __restrict__ o, int n)
{
    int i = blockIdx.x * blockDim.x + threadIdx.x;
    if (i < n) o[i] = __float2half(w[i]);
}

// ---------------- transpose input0 -> token-major fp32 ----------------
__global__ void xposeF_k(const float* __restrict__ in, float* __restrict__ out)
{
    __shared__ float t[32][33];
    int b = blockIdx.z;
    int tok0 = blockIdx.x * 32, ch0 = blockIdx.y * 32;
    int lx = threadIdx.x & 31, ly = threadIdx.x >> 5;
    #pragma unroll
    for (int i = 0; i < 4; i++) {
        int ch = ch0 + ly + i*8;
        t[lx][ly + i*8] = in[((size_t)b*256 + ch)*LSEQ + tok0 + lx];
    }
    __syncthreads();
    #pragma unroll
    for (int i = 0; i < 4; i++) {
        int tok = tok0 + ly + i*8;
        out[((size_t)b*LSEQ + tok)*256 + ch0 + lx] = t[ly + i*8][lx];
    }
}

// ---------------- layernorm, parallel: 16 tokens x 16-way channel split / block ----------------
__global__ void __launch_bounds__(256) ln_k(
    const float* __restrict__ in0, const float* __restrict__ in1,
    const float* __restrict__ w0, const float* __restrict__ b0,
    const float* __restrict__ w1, const float* __restrict__ b1,
    __nv_bfloat16* __restrict__ s0h, __nv_bfloat16* __restrict__ s0l,
    __nv_bfloat16* __restrict__ s1h, __nv_bfloat16* __restrict__ s1l)
{
    __shared__ float ssum[16][17], s2sum[16][17];
    __shared__ float mrs[2][16];
    __shared__ uint32_t spk[16][260];
    int which = blockIdx.y;
    const float* in = which ? in1 : in0;
    const float* w  = which ? w1  : w0;
    const float* bb = which ? b1  : b0;
    __nv_bfloat16* oh = which ? s1h : s0h;
    __nv_bfloat16* ol = which ? s1l : s0l;

    int tid = threadIdx.x;
    int tok = tid & 15, sub = tid >> 4;
    int idx = blockIdx.x * 16 + tok;
    int b = idx >> 12, l = idx & (LSEQ-1);
    const float* p = in + (size_t)b*DIMC*LSEQ + l;

    float vals[16];
    float s = 0.f, s2 = 0.f;
    #pragma unroll
    for (int j = 0; j < 16; j++) {
        float v = p[(size_t)(sub*16 + j)*LSEQ];
        vals[j] = v; s += v; s2 += v*v;
    }
    ssum[sub][tok] = s; s2sum[sub][tok] = s2;
    __syncthreads();
    if (tid < 16) {
        float S = 0.f, S2 = 0.f;
        #pragma unroll
        for (int u = 0; u < 16; u++) { S += ssum[u][tid]; S2 += s2sum[u][tid]; }
        float mean = S * (1.f/DIMC);
        float var  = S2 * (1.f/DIMC) - mean*mean;
        mrs[0][tid] = mean; mrs[1][tid] = rsqrtf(var + EPS_F);
    }
    __syncthreads();
    float mean = mrs[0][tok], rstd = mrs[1][tok];
    #pragma unroll
    for (int j = 0; j < 16; j++) {
        int c = sub*16 + j;
        spk[tok][c] = packsplit((vals[j] - mean) * rstd * w[c] + bb[c]);
    }
    __syncthreads();
    int trow = tid >> 5, cseg = (tid & 31) * 8;
    #pragma unroll
    for (int it = 0; it < 2; it++) {
        int tr = trow + it*8;
        size_t ob = (size_t)(blockIdx.x*16 + tr) * 256 + cseg;
        __align__(16) __nv_bfloat16 hh[8], ll[8];
        #pragma unroll
        for (int q = 0; q < 8; q++) {
            uint32_t pk = spk[tr][cseg + q];
            hh[q] = __ushort_as_bfloat16((unsigned short)(pk & 0xffff));
            ll[q] = __ushort_as_bfloat16((unsigned short)(pk >> 16));
        }
        *(uint4*)(oh + ob) = *(uint4*)hh;
        *(uint4*)(ol + ob) = *(uint4*)ll;
    }
}

// ---------------- depthwise causal conv (K=4) + silu — both dirs ----------------
__global__ void conv_silu_k(const float* __restrict__ x,
                            const float* __restrict__ wf, const float* __restrict__ bf,
                            const float* __restrict__ wb, const float* __restrict__ bbias,
                            float* __restrict__ xc)
{
    int t   = blockIdx.x * blockDim.x + threadIdx.x;
    int bdd = blockIdx.y;
    int dir = bdd >> 9;
    int bd  = bdd & 511;
    int d   = bd & 255;
    const float* w  = dir ? wb : wf;
    const float* bi = dir ? bbias : bf;
    const float* xp = x + (size_t)bd*LSEQ;
    float acc = bi[d];
    #pragma unroll
    for (int k = 0; k < 4; k++) {
        int s = t - 3 + k;
        if (s >= 0) {
            int ph = dir ? (LSEQ-1-s) : s;
            acc += w[d*4+k] * xp[ph];
        }
    }
    xc[(size_t)bdd*LSEQ + t] = acc * sigmoidf_(acc);
}

// ---------------- fp32 SGEMM (xproj / dtproj), per-dir weight select ----------------
enum { EP_NONE=0, EP_SPBIAS=1 };

template<int EP>
__global__ void __launch_bounds__(256) sgemm_k(
    const float* __restrict__ A0, const float* __restrict__ A1, int lda,
    const float* __restrict__ B, int ldb, long long bStride,
    float* __restrict__ C, int ldc, long long cStride,
    int M, int Kdim,
    const float* __restrict__ bias0, const float* __restrict__ bias1)
{
    __shared__ float As[8][128];
    __shared__ float Bs[8][128];
    int zb = blockIdx.z;
    int dir = zb >> 1;
    const float* A = dir ? A1 : A0;
    const float* bias = dir ? bias1 : bias0;
    B += (size_t)zb * bStride;
    C += (size_t)zb * cStride;

    int m0 = blockIdx.y * 128;
    int n0 = blockIdx.x * 128;
    int tid = threadIdx.x;
    int ar  = tid >> 1, ac = (tid & 1) << 2;
    int brr = tid >> 5, bc = (tid & 31) << 2;
    int mt0 = (tid >> 4) << 2, nt0 = (tid & 15) << 2;

    unsigned long long acc[8][4];
    #pragma unroll
    for (int i = 0; i < 8; i++)
        #pragma unroll
        for (int j = 0; j < 4; j++) acc[i][j] = 0ull;

    for (int k0 = 0; k0 < Kdim; k0 += 8) {
        float4 a4 = make_float4(0.f,0.f,0.f,0.f);
        int arow = m0 + ar;
        if (arow < M) a4 = *(const float4*)(A + (size_t)arow*lda + (k0 + ac));
        As[ac+0][ar] = a4.x; As[ac+1][ar] = a4.y; As[ac+2][ar] = a4.z; As[ac+3][ar] = a4.w;
        float4 b4 = *(const float4*)(B + (size_t)(k0 + brr)*ldb + (n0 + bc));
        *(float4*)&Bs[brr][bc] = b4;
        __syncthreads();
        #pragma unroll
        for (int kk = 0; kk < 8; kk++) {
            float4 aL = *(const float4*)&As[kk][mt0];
            float4 aH = *(const float4*)&As[kk][mt0+64];
            float av[8] = {aL.x,aL.y,aL.z,aL.w,aH.x,aH.y,aH.z,aH.w};
            unsigned long long b2[4];
            const unsigned long long* bpL = (const unsigned long long*)&Bs[kk][nt0];
            const unsigned long long* bpH = (const unsigned long long*)&Bs[kk][nt0+64];
            b2[0] = bpL[0]; b2[1] = bpL[1]; b2[2] = bpH[0]; b2[3] = bpH[1];
            #pragma unroll
            for (int i = 0; i < 8; i++) {
                unsigned long long a2;
                asm("mov.b64 %0, {%1, %1};" : "=l"(a2) : "f"(av[i]));
                #pragma unroll
                for (int j = 0; j < 4; j++)
                    asm("fma.rn.f32x2 %0, %1, %2, %0;" : "+l"(acc[i][j]) : "l"(a2), "l"(b2[j]));
            }
        }
        __syncthreads();
    }

    #pragma unroll
    for (int i = 0; i < 8; i++) {
        int m = m0 + ((i < 4) ? (mt0 + i) : (64 + mt0 + i - 4));
        if (m >= M) continue;
        float bv = (EP == EP_SPBIAS) ? bias[m] : 0.f;
        #pragma unroll
        for (int j = 0; j < 4; j++) {
            int n = n0 + ((j < 2) ? (nt0 + 2*j) : (64 + nt0 + 2*(j-2)));
            float2 v;
            asm("mov.b64 {%0, %1}, %2;" : "=f"(v.x), "=f"(v.y) : "l"(acc[i][j]));
            if (EP == EP_SPBIAS) { v.x = softplusf_(v.x + bv); v.y = softplusf_(v.y + bv); }
            *(float2*)(C + (size_t)m*ldc + n) = v;
        }
    }
}

// ---------------- chunked selective scan (both dirs in one launch) ----------------
__global__ void __launch_bounds__(256) scanA_k(
    const float* __restrict__ dt, const float* __restrict__ xc,
    const float* __restrict__ dbl,
    const float* __restrict__ A0, const float* __restrict__ A1,
    float* __restrict__ P, float* __restrict__ S)
{
    __shared__ float sdt[32][65], sx[32][65], sB[8][65];
    int chunk = blockIdx.x, zd = blockIdx.y, d0 = blockIdx.z * 32;
    int dir = zd >> 1, b = zd & 1;
    const float* Alog = dir ? A1 : A0;
    int tid = threadIdx.x;
    size_t base = ((size_t)(zd*DIMC + d0))*LSEQ + chunk*64;
    for (int i = tid; i < 2048; i += 256) {
        int r = i >> 6, c = i & 63;
        sdt[r][c] = dt[base + (size_t)r*LSEQ + c];
        sx [r][c] = xc[base + (size_t)r*LSEQ + c];
    }
    size_t bbase = ((size_t)(zd*32 + 16))*LSEQ + chunk*64;
    for (int i = tid; i < 512; i += 256) {
        int r = i >> 6, c = i & 63;
        sB[r][c] = dbl[bbase + (size_t)r*LSEQ + c];
    }
    __syncthreads();
    int dl = tid >> 3, n = tid & 7;
    float Aa = -__expf(Alog[(d0+dl)*8 + n]);
    float Pv = 1.f, Sv = 0.f;
    #pragma unroll 8
    for (int t = 0; t < 64; t++) {
        float dtv = sdt[dl][t];
        float dA  = __expf(dtv * Aa);
        Sv = Sv*dA + dtv * sx[dl][t] * sB[n][t];
        Pv *= dA;
    }
    size_t o = (size_t)dir*SCN_ + (((size_t)chunk*BATCH + b)*DIMC + d0+dl)*8 + n;
    P[o] = Pv; S[o] = Sv;
}

__global__ void scanB_k(const float* __restrict__ P, const float* __restrict__ S,
                        float* __restrict__ Hi)
{
    int gid = blockIdx.x * blockDim.x + threadIdx.x;
    int dir = gid >> 12, idx = gid & 4095;
    const float* Pd = P + (size_t)dir*SCN_;
    const float* Sd = S + (size_t)dir*SCN_;
    float* Hd = Hi + (size_t)dir*SCN_;
    float h = 0.f;
    for (int c0 = 0; c0 < 64; c0 += 8) {
        float p[8], s[8];
        #pragma unroll
        for (int j = 0; j < 8; j++) {
            size_t o = (size_t)(c0+j)*4096 + idx;
            p[j] = Pd[o]; s[j] = Sd[o];
        }
        #pragma unroll
        for (int j = 0; j < 8; j++) {
            Hd[(size_t)(c0+j)*4096 + idx] = h;
            h = h * p[j] + s[j];
        }
    }
}

__global__ void __launch_bounds__(256) scanC_k(
    const float* __restrict__ dt, const float* __restrict__ xc,
    const float* __restrict__ dbl,
    const float* __restrict__ A0, const float* __restrict__ A1,
    const float* __restrict__ Hi,
    const float* __restrict__ D0, const float* __restrict__ D1,
    const float* __restrict__ z, float* __restrict__ y)
{
    __shared__ float sdt[32][65], sx[32][65], sB[8][65], sC[8][65];
    __shared__ float sy[32][64];
    int chunk = blockIdx.x, zd = blockIdx.y, d0 = blockIdx.z * 32;
    int dir = zd >> 1, b = zd & 1;
    const float* Alog = dir ? A1 : A0;
    const float* Dp   = dir ? D1 : D0;
    int tid = threadIdx.x;
    size_t base = ((size_t)(zd*DIMC + d0))*LSEQ + chunk*64;
    for (int i = tid; i < 2048; i += 256) {
        int r = i >> 6, c = i & 63;
        sdt[r][c] = dt[base + (size_t)r*LSEQ + c];
        sx [r][c] = xc[base + (size_t)r*LSEQ + c];
    }
    size_t bbase = ((size_t)(zd*32 + 16))*LSEQ + chunk*64;
    size_t cbase = ((size_t)(zd*32 + 24))*LSEQ + chunk*64;
    for (int i = tid; i < 512; i += 256) {
        int r = i >> 6, c = i & 63;
        sB[r][c] = dbl[bbase + (size_t)r*LSEQ + c];
        sC[r][c] = dbl[cbase + (size_t)r*LSEQ + c];
    }
    __syncthreads();
    int dl = tid >> 3, n = tid & 7;
    float Aa = -__expf(Alog[(d0+dl)*8 + n]);
    float h = Hi[(size_t)dir*SCN_ + (((size_t)chunk*BATCH + b)*DIMC + d0+dl)*8 + n];
    for (int t = 0; t < 64; t++) {
        float dtv = sdt[dl][t];
        float dA  = __expf(dtv * Aa);
        h = h*dA + dtv * sx[dl][t] * sB[n][t];
        float yv = h * sC[n][t];
        yv += __shfl_down_sync(0xffffffffu, yv, 4);
        yv += __shfl_down_sync(0xffffffffu, yv, 2);
        yv += __shfl_down_sync(0xffffffffu, yv, 1);
        if (n == 0) sy[dl][t] = yv;
    }
    __syncthreads();
    float* yD = y + (size_t)dir * BATCH*DIMC*LSEQ;
    for (int i = tid; i < 2048; i += 256) {
        int r = i >> 6, c = i & 63;
        int tl = chunk*64 + c;
        int lp = dir ? (LSEQ-1-tl) : tl;
        size_t gi = ((size_t)(b*DIMC + d0 + r))*LSEQ + lp;
        float v = sy[r][c] + sx[r][c]*Dp[d0+r];
        float zz = z[gi];
        yD[gi] = v * zz * sigmoidf_(zz);
    }
}

// ---------------- rmsnorm 3 heads, parallel: 16 tokens x 16-way split / block ----------------
__global__ void __launch_bounds__(256) rms3_k(
    const float* __restrict__ yf, const float* __restrict__ yb,
    const float* __restrict__ w,
    __nv_bfloat16* __restrict__ ynh, __nv_bfloat16* __restrict__ ynl)
{
    __shared__ float red[3][16][17];
    __shared__ float rfac[3][16];
    __shared__ uint32_t spk[16][260];
    int tid = threadIdx.x;
    int tok = tid & 15, sub = tid >> 4;
    int idx = blockIdx.x * 16 + tok;
    int b = idx >> 12, l = idx & (LSEQ-1);
    size_t base = (size_t)b*DIMC*LSEQ + l;

    float vf[16], vb[16], wv[16];
    float sa = 0.f, sf = 0.f, sb = 0.f;
    #pragma unroll
    for (int j = 0; j < 16; j++) {
        int c = sub*16 + j;
        float f = yf[base + (size_t)c*LSEQ];
        float bk = yb[base + (size_t)c*LSEQ];
        vf[j] = f; vb[j] = bk; wv[j] = w[c];
        float va = 0.5f*(f + bk);
        sa += va*va; sf += f*f; sb += bk*bk;
    }
    red[0][sub][tok] = sa; red[1][sub][tok] = sf; red[2][sub][tok] = sb;
    __syncthreads();
    if (tid < 48) {
        int hh = tid >> 4, tt = tid & 15;
        float S = 0.f;
        #pragma unroll
        for (int u = 0; u < 16; u++) S += red[hh][u][tt];
        rfac[hh][tt] = rsqrtf(S * (1.f/DIMC) + EPS_F);
    }
    __syncthreads();

    int trow = tid >> 5, cseg = (tid & 31) * 8;
    #pragma unroll 1
    for (int h = 0; h < 3; h++) {
        float r = rfac[h][tok];
        #pragma unroll
        for (int j = 0; j < 16; j++) {
            int c = sub*16 + j;
            float v = (h == 0) ? 0.5f*(vf[j] + vb[j]) : (h == 1) ? vf[j] : vb[j];
            spk[tok][c] = packsplit(v * r * wv[j]);
        }
        __syncthreads();
        #pragma unroll
        for (int it = 0; it < 2; it++) {
            int tr = trow + it*8;
            int idx2 = blockIdx.x*16 + tr;
            int b2 = idx2 >> 12, l2 = idx2 & (LSEQ-1);
            size_t ob = ((size_t)(h*2 + b2)*LSEQ + l2) * 256 + cseg;
            __align__(16) __nv_bfloat16 hh8[8], ll8[8];
            #pragma unroll
            for (int q = 0; q < 8; q++) {
                uint32_t pk = spk[tr][cseg + q];
                hh8[q] = __ushort_as_bfloat16((unsigned short)(pk & 0xffff));
                ll8[q] = __ushort_as_bfloat16((unsigned short)(pk >> 16));
            }
            *(uint4*)(ynh + ob) = *(uint4*)hh8;
            *(uint4*)(ynl + ob) = *(uint4*)ll8;
        }
        __syncthreads();
    }
}

// ---------------- launch ----------------
extern "C" void kernel_launch(void* const* d_in, const int* in_sizes, int n_in,
                              void* d_out, int out_size)
{
    (void)in_sizes; (void)n_in; (void)out_size;
    const float* input0      = (const float*)d_in[0];
    const float* input1      = (const float*)d_in[1];
    const float* norm0_w     = (const float*)d_in[2];
    const float* norm0_b     = (const float*)d_in[3];
    const float* norm1_w     = (const float*)d_in[4];
    const float* norm1_b     = (const float*)d_in[5];
    const float* in_proj_w   = (const float*)d_in[6];
    const float* in_projz_w  = (const float*)d_in[7];
    const float* conv1d_w    = (const float*)d_in[8];
    const float* conv1d_bias = (const float*)d_in[9];
    const float* conv1db_w   = (const float*)d_in[10];
    const float* conv1db_bias= (const float*)d_in[11];
    const float* xproj_w     = (const float*)d_in[12];
    const float* xprojb_w    = (const float*)d_in[13];
    const float* dtproj_w    = (const float*)d_in[14];
    const float* dtproj_bias = (const float*)d_in[15];
    const float* dtprojb_w   = (const float*)d_in[16];
    const float* dtprojb_bias= (const float*)d_in[17];
    const float* A_log       = (const float*)d_in[18];
    const float* Ab_log      = (const float*)d_in[19];
    const float* D_p         = (const float*)d_in[20];
    const float* D_b         = (const float*)d_in[21];
    const float* rms_w       = (const float*)d_in[22];
    const float* out_proj_w  = (const float*)d_in[23];
    const float* conv3d_w    = (const float*)d_in[24];
    const float* conv3d_bias = (const float*)d_in[25];
    float* out = (float*)d_out;

    float *x_, *z_, *xc_, *dbl_, *dt_, *P_, *S_, *Hi_, *y_, *skipT;
    __nv_bfloat16 *s0h,*s0l,*s1h,*s1l,*ynh,*ynl;
    __half *of_, *wc3f;
    __nv_bfloat16 *wip_h,*wip_l,*wiz_h,*wiz_l,*wop_h,*wop_l;
    cudaGetSymbolAddress((void**)&x_,   g_x);
    cudaGetSymbolAddress((void**)&z_,   g_z);
    cudaGetSymbolAddress((void**)&xc_,  g_xc);
    cudaGetSymbolAddress((void**)&dbl_, g_dbl);
    cudaGetSymbolAddress((void**)&dt_,  g_dt);
    cudaGetSymbolAddress((void**)&P_,   g_P);
    cudaGetSymbolAddress((void**)&S_,   g_S);
    cudaGetSymbolAddress((void**)&Hi_,  g_Hi);
    cudaGetSymbolAddress((void**)&y_,   g_y);
    cudaGetSymbolAddress((void**)&skipT,g_skipT);
    cudaGetSymbolAddress((void**)&s0h,  g_s0h);
    cudaGetSymbolAddress((void**)&s0l,  g_s0l);
    cudaGetSymbolAddress((void**)&s1h,  g_s1h);
    cudaGetSymbolAddress((void**)&s1l,  g_s1l);
    cudaGetSymbolAddress((void**)&ynh,  g_ynh);
    cudaGetSymbolAddress((void**)&ynl,  g_ynl);
    cudaGetSymbolAddress((void**)&of_,  g_of);
    cudaGetSymbolAddress((void**)&wc3f, g_wc3f);
    cudaGetSymbolAddress((void**)&wip_h, g_wip_h); cudaGetSymbolAddress((void**)&wip_l, g_wip_l);
    cudaGetSymbolAddress((void**)&wiz_h, g_wiz_h); cudaGetSymbolAddress((void**)&wiz_l, g_wiz_l);
    cudaGetSymbolAddress((void**)&wop_h, g_wop_h); cudaGetSymbolAddress((void**)&wop_l, g_wop_l);

    const int TCSMEM  = 2 * STG;    // 110592
    const int TCSMEMH = 2 * STGH;   // 55296
    cudaFuncSetAttribute(tcgemm_k<EPT_XPOSE>, cudaFuncAttributeMaxDynamicSharedMemorySize, TCSMEM);
    cudaFuncSetAttribute(tcgemm_k<EPT_SKIP>,  cudaFuncAttributeMaxDynamicSharedMemorySize, TCSMEM);
    cudaFuncSetAttribute(tcgemmH_k,           cudaFuncAttributeMaxDynamicSharedMemorySize, TCSMEMH);

    const long long SB  = (long long)DIMC*LSEQ;
    const long long SB32= (long long)32*LSEQ;

    // 0) weight converts + skip transpose
    wsplit3_k<<<dim3(256,3), 256>>>(in_proj_w, in_projz_w, out_proj_w,
                                    wip_h, wip_l, wiz_h, wiz_l, wop_h, wop_l);
    wc3f_k<<<1200, 256>>>(conv3d_w, wc3f, 307200);
    xposeF_k<<<dim3(128,8,2), 256>>>(input0, skipT);

    // 1) layernorms -> token-major bf16 hi/lo (parallelized)
    ln_k<<<dim3(512,2), 256>>>(input0, input1, norm0_w, norm0_b, norm1_w, norm1_b,
                               s0h, s0l, s1h, s1l);

    // 2) in_proj / in_projz (3-pass bf16) -> channel-major fp32
    tcgemm_k<EPT_XPOSE><<<dim3(4,32,2), 256, TCSMEM>>>(s0h, s0l, wip_h, wip_l, 256,
                                                       x_, nullptr, nullptr);
    tcgemm_k<EPT_XPOSE><<<dim3(4,32,2), 256, TCSMEM>>>(s1h, s1l, wiz_h, wiz_l, 256,
                                                       z_, nullptr, nullptr);

    // 3) conv + silu, both dirs
    conv_silu_k<<<dim3(16,1024), 256>>>(x_, conv1d_w, conv1d_bias, conv1db_w, conv1db_bias,
                                        (float*)xc_);
    // 4) xproj, both dirs
    sgemm_k<EP_NONE><<<dim3(32,1,4), 256>>>(xproj_w, xprojb_w, 256,
                                            xc_, LSEQ, SB, dbl_, LSEQ, SB32,
                                            32, 256, nullptr, nullptr);
    // 5) dtproj + softplus, both dirs
    sgemm_k<EP_SPBIAS><<<dim3(32,2,4), 256>>>(dtproj_w, dtprojb_w, 16,
                                              dbl_, LSEQ, SB32, dt_, LSEQ, SB,
                                              256, 16, dtproj_bias, dtprojb_bias);
    // 6) chunked scan, both dirs
    scanA_k<<<dim3(64,4,8), 256>>>(dt_, xc_, dbl_, A_log, Ab_log, P_, S_);
    scanB_k<<<32, 256>>>(P_, S_, Hi_);
    scanC_k<<<dim3(64,4,8), 256>>>(dt_, xc_, dbl_, A_log, Ab_log, Hi_, D_p, D_b, z_, y_);

    // 7) rmsnorm 3 heads (parallelized)
    rms3_k<<<512, 256>>>(y_, y_ + (size_t)BATCH*DIMC*LSEQ, rms_w, ynh, ynl);

    // 8) out_proj (+skip) (3-pass bf16) -> token-major fp16 o
    tcgemm_k<EPT_SKIP><<<dim3(4,32,6), 256, TCSMEM>>>(ynh, ynl, wop_h, wop_l, 256,
                                                      nullptr, skipT, of_);

    // 9) conv3d (1-pass fp16, +bias) -> final output (channel-major fp32)
    tcgemmH_k<<<dim3(19,32,6), 256, TCSMEMH>>>(of_, wc3f, 1200, out, conv3d_bias);
}

// round 15
// speedup vs baseline: 2.0577x; 1.0797x over previous
#include <cuda_runtime.h>
#include <cuda_bf16.h>
#include <cuda_fp16.h>
#include <cstdint>
#include <math.h>

#define LSEQ 4096
#define BATCH 2
#define DIMC 256
#define EPS_F 1e-5f
#define SCN_ (64*BATCH*DIMC*8)

// ---------------- scratch (device globals) ----------------
__device__ float g_x   [BATCH*DIMC*LSEQ];
__device__ float g_z   [BATCH*DIMC*LSEQ];
__device__ float g_xc  [2][BATCH*DIMC*LSEQ];
__device__ float g_dbl [2][BATCH*32*LSEQ];
__device__ float g_dt  [2][BATCH*DIMC*LSEQ];
__device__ float g_P   [2][SCN_];
__device__ float g_S   [2][SCN_];
__device__ float g_Hi  [2][SCN_];
__device__ float g_y   [2][BATCH*DIMC*LSEQ];
__device__ float g_skipT[BATCH*LSEQ*DIMC];

__device__ __nv_bfloat16 g_s0h[BATCH*LSEQ*DIMC], g_s0l[BATCH*LSEQ*DIMC];
__device__ __nv_bfloat16 g_s1h[BATCH*LSEQ*DIMC], g_s1l[BATCH*LSEQ*DIMC];
__device__ __half        g_ynf[6*LSEQ*DIMC];          // rmsnorm result, fp16
__device__ __half        g_of [6*LSEQ*DIMC];          // out_proj(+skip) result, fp16
__device__ __nv_bfloat16 g_wip_h[DIMC*DIMC], g_wip_l[DIMC*DIMC];
__device__ __nv_bfloat16 g_wiz_h[DIMC*DIMC], g_wiz_l[DIMC*DIMC];
__device__ __half        g_wopf[DIMC*DIMC];           // out_proj weight, fp16
__device__ __half        g_wc3f[1200*DIMC];           // conv3d weight, fp16

__device__ __forceinline__ float sigmoidf_(float x){ return 1.f/(1.f+__expf(-x)); }
__device__ __forceinline__ float softplusf_(float x){ return x>20.f ? x : log1pf(__expf(x)); }

__device__ __forceinline__ void bf16split(float v, __nv_bfloat16& h, __nv_bfloat16& l) {
    h = __float2bfloat16(v);
    l = __float2bfloat16(v - __bfloat162float(h));
}
__device__ __forceinline__ uint32_t packsplit(float v) {
    __nv_bfloat16 h, l; bf16split(v, h, l);
    return (uint32_t)__bfloat16_as_ushort(h) | ((uint32_t)__bfloat16_as_ushort(l) << 16);
}

__device__ __forceinline__ uint32_t smem_u32(const void* p) {
    uint32_t a;
    asm("{ .reg .u64 t; cvta.to.shared.u64 t, %1; cvt.u32.u64 %0, t; }" : "=r"(a) : "l"(p));
    return a;
}
__device__ __forceinline__ void ldmx4(uint32_t* r, uint32_t addr) {
    asm volatile("ldmatrix.sync.aligned.m8n8.x4.shared.b16 {%0,%1,%2,%3}, [%4];"
        : "=r"(r[0]),"=r"(r[1]),"=r"(r[2]),"=r"(r[3]) : "r"(addr));
}
__device__ __forceinline__ void mma16816(float* d, const uint32_t* a, uint32_t b0, uint32_t b1) {
    asm volatile("mma.sync.aligned.m16n8k16.row.col.f32.bf16.bf16.f32 "
        "{%0,%1,%2,%3}, {%4,%5,%6,%7}, {%8,%9}, {%0,%1,%2,%3};"
        : "+f"(d[0]),"+f"(d[1]),"+f"(d[2]),"+f"(d[3])
        : "r"(a[0]),"r"(a[1]),"r"(a[2]),"r"(a[3]), "r"(b0),"r"(b1));
}
__device__ __forceinline__ void mma16816h(float* d, const uint32_t* a, uint32_t b0, uint32_t b1) {
    asm volatile("mma.sync.aligned.m16n8k16.row.col.f32.f16.f16.f32 "
        "{%0,%1,%2,%3}, {%4,%5,%6,%7}, {%8,%9}, {%0,%1,%2,%3};"
        : "+f"(d[0]),"+f"(d[1]),"+f"(d[2]),"+f"(d[3])
        : "r"(a[0]),"r"(a[1]),"r"(a[2]),"r"(a[3]), "r"(b0),"r"(b1));
}
__device__ __forceinline__ void cp16(uint32_t dst, const void* src, int sz) {
    asm volatile("cp.async.cg.shared.global [%0], [%1], 16, %2;"
        :: "r"(dst), "l"(__cvta_generic_to_global(src)), "r"(sz) : "memory");
}

#define TILE_A  18432
#define TILE_BB 9216
#define STG     (2*TILE_A + 2*TILE_BB)   // 55296

// ---------------- split-bf16 GEMM (3-pass) for in_proj / in_projz, merged z=4 ----------------
__global__ void __launch_bounds__(256, 2) tcgemm_k(
    const __nv_bfloat16* __restrict__ A0h, const __nv_bfloat16* __restrict__ A0l,
    const __nv_bfloat16* __restrict__ B0h, const __nv_bfloat16* __restrict__ B0l,
    const __nv_bfloat16* __restrict__ A1h, const __nv_bfloat16* __restrict__ A1l,
    const __nv_bfloat16* __restrict__ B1h, const __nv_bfloat16* __restrict__ B1l,
    float* __restrict__ out0, float* __restrict__ out1)
{
    extern __shared__ char smem[];
    const int tid = threadIdx.x, lane = tid & 31, warp = tid >> 5;
    const int mw = warp & 3, nw = warp >> 2;
    const int n0 = blockIdx.x * 64, tl0 = blockIdx.y * 128, zb = blockIdx.z;
    const int which = zb >> 1, zloc = zb & 1;
    const __nv_bfloat16* Ah = which ? A1h : A0h;
    const __nv_bfloat16* Al = which ? A1l : A0l;
    const __nv_bfloat16* Bh = which ? B1h : B0h;
    const __nv_bfloat16* Bl = which ? B1l : B0l;
    float* outF = which ? out1 : out0;
    const long long t0 = (long long)zloc * LSEQ + tl0;

    float acc[2][4][4];
    #pragma unroll
    for (int i = 0; i < 2; i++)
        #pragma unroll
        for (int j = 0; j < 4; j++)
            #pragma unroll
            for (int c = 0; c < 4; c++) acc[i][j][c] = 0.f;

    const uint32_t sbase = smem_u32(smem);
    const int a_row  = (lane & 7) + ((lane >> 3) & 1) * 8;
    const int a_kadd = (lane >> 4) * 8;
    const int b_row  = (lane & 7) + (lane >> 4) * 8;
    const int b_kadd = ((lane >> 3) & 1) * 8;
    const uint32_t aoffH = sbase + 0        + (uint32_t)((mw*32 + a_row)*72 + a_kadd) * 2;
    const uint32_t boffH = sbase + 2*TILE_A + (uint32_t)((nw*32 + b_row)*72 + b_kadd) * 2;

    const int lrow = tid >> 3, lc8 = (tid & 7) * 8;

    auto load_chunk = [&](int kc, int stage) {
        const int kofs = kc * 64;
        const uint32_t sb0 = sbase + stage * STG;
        #pragma unroll
        for (int it = 0; it < 4; it++) {
            int row = lrow + it * 32;
            uint32_t sa = sb0 + (uint32_t)(row * 72 + lc8) * 2;
            cp16(sa,          Ah + (t0 + row) * 256 + kofs + lc8, 16);
            cp16(sa + TILE_A, Al + (t0 + row) * 256 + kofs + lc8, 16);
        }
        #pragma unroll
        for (int it = 0; it < 2; it++) {
            int row = lrow + it * 32;
            uint32_t sa = sb0 + 2*TILE_A + (uint32_t)(row * 72 + lc8) * 2;
            int brow = n0 + row;
            cp16(sa,           Bh + (size_t)brow * 256 + kofs + lc8, 16);
            cp16(sa + TILE_BB, Bl + (size_t)brow * 256 + kofs + lc8, 16);
        }
    };

    auto compute = [&](int stage) {
        const uint32_t sadd = (uint32_t)stage * STG;
        #pragma unroll
        for (int ks = 0; ks < 4; ks++) {
            const uint32_t k2 = (uint32_t)(ks * 16) * 2;
            uint32_t aH[2][4], aL[2][4];
            #pragma unroll
            for (int i = 0; i < 2; i++) {
                ldmx4(aH[i], aoffH + sadd + i*16*144 + k2);
                ldmx4(aL[i], aoffH + sadd + TILE_A + i*16*144 + k2);
            }
            uint32_t bH[2][4], bL[2][4];
            #pragma unroll
            for (int g = 0; g < 2; g++) {
                ldmx4(bH[g], boffH + sadd + g*16*144 + k2);
                ldmx4(bL[g], boffH + sadd + TILE_BB + g*16*144 + k2);
            }
            #pragma unroll
            for (int i = 0; i < 2; i++)
                #pragma unroll
                for (int g = 0; g < 2; g++)
                    #pragma unroll
                    for (int p = 0; p < 2; p++) {
                        int j4 = g*2 + p;
                        mma16816(acc[i][j4], aH[i], bH[g][2*p], bH[g][2*p+1]);
                        mma16816(acc[i][j4], aH[i], bL[g][2*p], bL[g][2*p+1]);
                        mma16816(acc[i][j4], aL[i], bH[g][2*p], bH[g][2*p+1]);
                    }
        }
    };

    load_chunk(0, 0);
    asm volatile("cp.async.commit_group;" ::: "memory");
    for (int kc = 0; kc < 4; kc++) {
        if (kc < 3) {
            load_chunk(kc + 1, (kc + 1) & 1);
            asm volatile("cp.async.commit_group;" ::: "memory");
            asm volatile("cp.async.wait_group 1;" ::: "memory");
        } else {
            asm volatile("cp.async.wait_group 0;" ::: "memory");
        }
        __syncthreads();
        compute(kc & 1);
        __syncthreads();
    }

    // channel-major fp32 via smem transpose
    float* sbuf = (float*)smem;
    __syncthreads();
    #pragma unroll
    for (int i = 0; i < 2; i++)
        #pragma unroll
        for (int j4 = 0; j4 < 4; j4++)
            #pragma unroll
            for (int rr = 0; rr < 2; rr++) {
                int tok = mw*32 + i*16 + (lane >> 2) + rr*8;
                int nl = nw*32 + j4*8 + 2*(lane & 3);
                sbuf[nl*132 + tok]     = acc[i][j4][rr*2+0];
                sbuf[(nl+1)*132 + tok] = acc[i][j4][rr*2+1];
            }
    __syncthreads();
    int row = tid >> 2;
    int n = n0 + row;
    const float* srcr = sbuf + row*132;
    float* dstr = outF + ((size_t)zloc * 256 + n) * LSEQ + tl0;
    int c0 = (tid & 3) * 4;
    #pragma unroll
    for (int q = 0; q < 8; q++) {
        int col = c0 + q*16;
        *(float4*)(dstr + col) = *(const float4*)(srcr + col);
    }
}

// ---------------- single-pass fp16 GEMM (out_proj & conv3d), cp.async double-buffered ----------------
#define EPH_SKIP 0
#define EPH_BIAS 1
#define STGH (TILE_A + TILE_BB)   // 27648

template<int EPH>
__global__ void __launch_bounds__(256, 2) tcgemmH_k(
    const __half* __restrict__ A, const __half* __restrict__ W, int bRows,
    float* __restrict__ outF, const float* __restrict__ bias,
    const float* __restrict__ skipT, __half* __restrict__ Of)
{
    extern __shared__ char smem[];
    const int tid = threadIdx.x, lane = tid & 31, warp = tid >> 5;
    const int mw = warp & 3, nw = warp >> 2;
    const int n0 = blockIdx.x * 64, tl0 = blockIdx.y * 128, zb = blockIdx.z;
    const long long t0 = (long long)zb * LSEQ + tl0;

    float acc[2][4][4];
    #pragma unroll
    for (int i = 0; i < 2; i++)
        #pragma unroll
        for (int j = 0; j < 4; j++)
            #pragma unroll
            for (int c = 0; c < 4; c++) acc[i][j][c] = 0.f;

    const uint32_t sbase = smem_u32(smem);
    const int a_row  = (lane & 7) + ((lane >> 3) & 1) * 8;
    const int a_kadd = (lane >> 4) * 8;
    const int b_row  = (lane & 7) + (lane >> 4) * 8;
    const int b_kadd = ((lane >> 3) & 1) * 8;
    const uint32_t aoff = sbase + 0      + (uint32_t)((mw*32 + a_row)*72 + a_kadd) * 2;
    const uint32_t boff = sbase + TILE_A + (uint32_t)((nw*32 + b_row)*72 + b_kadd) * 2;

    const int lrow = tid >> 3, lc8 = (tid & 7) * 8;

    auto load_chunk = [&](int kc, int stage) {
        const int kofs = kc * 64;
        const uint32_t sb0 = sbase + stage * STGH;
        #pragma unroll
        for (int it = 0; it < 4; it++) {
            int row = lrow + it * 32;
            cp16(sb0 + (uint32_t)(row * 72 + lc8) * 2, A + (t0 + row) * 256 + kofs + lc8, 16);
        }
        #pragma unroll
        for (int it = 0; it < 2; it++) {
            int row = lrow + it * 32;
            int brow = n0 + row;
            int ok = (brow < bRows) ? 16 : 0;
            if (brow >= bRows) brow = bRows - 1;
            cp16(sb0 + TILE_A + (uint32_t)(row * 72 + lc8) * 2,
                 W + (size_t)brow * 256 + kofs + lc8, ok);
        }
    };

    auto compute = [&](int stage) {
        const uint32_t sadd = (uint32_t)stage * STGH;
        #pragma unroll
        for (int ks = 0; ks < 4; ks++) {
            const uint32_t k2 = (uint32_t)(ks * 16) * 2;
            uint32_t aF[2][4], bF[2][4];
            #pragma unroll
            for (int i = 0; i < 2; i++) ldmx4(aF[i], aoff + sadd + i*16*144 + k2);
            #pragma unroll
            for (int g = 0; g < 2; g++) ldmx4(bF[g], boff + sadd + g*16*144 + k2);
            #pragma unroll
            for (int i = 0; i < 2; i++)
                #pragma unroll
                for (int g = 0; g < 2; g++)
                    #pragma unroll
                    for (int p = 0; p < 2; p++)
                        mma16816h(acc[i][g*2+p], aF[i], bF[g][2*p], bF[g][2*p+1]);
        }
    };

    load_chunk(0, 0);
    asm volatile("cp.async.commit_group;" ::: "memory");
    for (int kc = 0; kc < 4; kc++) {
        if (kc < 3) {
            load_chunk(kc + 1, (kc + 1) & 1);
            asm volatile("cp.async.commit_group;" ::: "memory");
            asm volatile("cp.async.wait_group 1;" ::: "memory");
        } else {
            asm volatile("cp.async.wait_group 0;" ::: "memory");
        }
        __syncthreads();
        compute(kc & 1);
        __syncthreads();
    }

    if (EPH == EPH_SKIP) {
        // + skip (fp32, token-major) -> fp16 token-major
        #pragma unroll
        for (int i = 0; i < 2; i++)
            #pragma unroll
            for (int rr = 0; rr < 2; rr++) {
                int tok = tl0 + mw*32 + i*16 + (lane >> 2) + rr*8;
                size_t orow = ((size_t)zb * LSEQ + tok) * 256;
                size_t srow = ((size_t)(zb & 1) * LSEQ + tok) * 256;
                #pragma unroll
                for (int j4 = 0; j4 < 4; j4++) {
                    int n = n0 + nw*32 + j4*8 + 2*(lane & 3);
                    float2 sk = *(const float2*)(skipT + srow + n);
                    __half2 hv;
                    hv.x = __float2half(acc[i][j4][rr*2+0] + sk.x);
                    hv.y = __float2half(acc[i][j4][rr*2+1] + sk.y);
                    *(__half2*)(Of + orow + n) = hv;
                }
            }
    } else {
        // channel-major fp32 + bias via smem transpose
        float* sbuf = (float*)smem;
        __syncthreads();
        #pragma unroll
        for (int i = 0; i < 2; i++)
            #pragma unroll
            for (int j4 = 0; j4 < 4; j4++)
                #pragma unroll
                for (int rr = 0; rr < 2; rr++) {
                    int tok = mw*32 + i*16 + (lane >> 2) + rr*8;
                    int nl = nw*32 + j4*8 + 2*(lane & 3);
                    sbuf[nl*132 + tok]     = acc[i][j4][rr*2+0];
                    sbuf[(nl+1)*132 + tok] = acc[i][j4][rr*2+1];
                }
        __syncthreads();
        int row = tid >> 2;
        int n = n0 + row;
        if (n < bRows) {
            float bv = bias[n];
            const float* srcr = sbuf + row*132;
            float* dstr = outF + ((size_t)zb * bRows + n) * LSEQ + tl0;
            int c0 = (tid & 3) * 4;
            #pragma unroll
            for (int q = 0; q < 8; q++) {
                int col = c0 + q*16;
                float4 v = *(const float4*)(srcr + col);
                v.x += bv; v.y += bv; v.z += bv; v.w += bv;
                *(float4*)(dstr + col) = v;
            }
        }
    }
}

// ---------------- weight converts ----------------
__global__ void wsplit2_k(const float* __restrict__ w0, const float* __restrict__ w1,
                          __nv_bfloat16* __restrict__ h0, __nv_bfloat16* __restrict__ l0,
                          __nv_bfloat16* __restrict__ h1, __nv_bfloat16* __restrict__ l1)
{
    int seg = blockIdx.y;
    const float* w = seg ? w1 : w0;
    __nv_bfloat16* h = seg ? h1 : h0;
    __nv_bfloat16* l = seg ? l1 : l0;
    int i = blockIdx.x * blockDim.x + threadIdx.x;
    if (i < 65536) { __nv_bfloat16 hh, ll; bf16split(w[i], hh, ll); h[i] = hh; l[i] = ll; }
}
__global__ void whalf2_k(const float* __restrict__ w0, const float* __restrict__ w1,
                         __half* __restrict__ o0, __half* __restrict__ o1)
{
    int seg = blockIdx.y;
    const float* w = seg ? w1 : w0;
    __half* o = seg ? o1 : o0;
    int n = seg ? 65536 : 307200;
    int i = blockIdx.x * blockDim.x + threadIdx.x;
    if (i < n) o[i] = __float2half(w[i]);
}

// ---------------- transpose input0 -> token-major fp32 ----------------
__global__ void xposeF_k(const float* __restrict__ in, float* __restrict__ out)
{
    __shared__ float t[32][33];
    int b = blockIdx.z;
    int tok0 = blockIdx.x * 32, ch0 = blockIdx.y * 32;
    int lx = threadIdx.x & 31, ly = threadIdx.x >> 5;
    #pragma unroll
    for (int i = 0; i < 4; i++) {
        int ch = ch0 + ly + i*8;
        t[lx][ly + i*8] = in[((size_t)b*256 + ch)*LSEQ + tok0 + lx];
    }
    __syncthreads();
    #pragma unroll
    for (int i = 0; i < 4; i++) {
        int tok = tok0 + ly + i*8;
        out[((size_t)b*LSEQ + tok)*256 + ch0 + lx] = t[ly + i*8][lx];
    }
}

// ---------------- layernorm, parallel: 16 tokens x 16-way channel split / block ----------------
__global__ void __launch_bounds__(256) ln_k(
    const float* __restrict__ in0, const float* __restrict__ in1,
    const float* __restrict__ w0, const float* __restrict__ b0,
    const float* __restrict__ w1, const float* __restrict__ b1,
    __nv_bfloat16* __restrict__ s0h, __nv_bfloat16* __restrict__ s0l,
    __nv_bfloat16* __restrict__ s1h, __nv_bfloat16* __restrict__ s1l)
{
    __shared__ float ssum[16][17], s2sum[16][17];
    __shared__ float mrs[2][16];
    __shared__ uint32_t spk[16][260];
    int which = blockIdx.y;
    const float* in = which ? in1 : in0;
    const float* w  = which ? w1  : w0;
    const float* bb = which ? b1  : b0;
    __nv_bfloat16* oh = which ? s1h : s0h;
    __nv_bfloat16* ol = which ? s1l : s0l;

    int tid = threadIdx.x;
    int tok = tid & 15, sub = tid >> 4;
    int idx = blockIdx.x * 16 + tok;
    int b = idx >> 12, l = idx & (LSEQ-1);
    const float* p = in + (size_t)b*DIMC*LSEQ + l;

    float vals[16];
    float s = 0.f, s2 = 0.f;
    #pragma unroll
    for (int j = 0; j < 16; j++) {
        float v = p[(size_t)(sub*16 + j)*LSEQ];
        vals[j] = v; s += v; s2 += v*v;
    }
    ssum[sub][tok] = s; s2sum[sub][tok] = s2;
    __syncthreads();
    if (tid < 16) {
        float S = 0.f, S2 = 0.f;
        #pragma unroll
        for (int u = 0; u < 16; u++) { S += ssum[u][tid]; S2 += s2sum[u][tid]; }
        float mean = S * (1.f/DIMC);
        float var  = S2 * (1.f/DIMC) - mean*mean;
        mrs[0][tid] = mean; mrs[1][tid] = rsqrtf(var + EPS_F);
    }
    __syncthreads();
    float mean = mrs[0][tok], rstd = mrs[1][tok];
    #pragma unroll
    for (int j = 0; j < 16; j++) {
        int c = sub*16 + j;
        spk[tok][c] = packsplit((vals[j] - mean) * rstd * w[c] + bb[c]);
    }
    __syncthreads();
    int trow = tid >> 5, cseg = (tid & 31) * 8;
    #pragma unroll
    for (int it = 0; it < 2; it++) {
        int tr = trow + it*8;
        size_t ob = (size_t)(blockIdx.x*16 + tr) * 256 + cseg;
        __align__(16) __nv_bfloat16 hh[8], ll[8];
        #pragma unroll
        for (int q = 0; q < 8; q++) {
            uint32_t pk = spk[tr][cseg + q];
            hh[q] = __ushort_as_bfloat16((unsigned short)(pk & 0xffff));
            ll[q] = __ushort_as_bfloat16((unsigned short)(pk >> 16));
        }
        *(uint4*)(oh + ob) = *(uint4*)hh;
        *(uint4*)(ol + ob) = *(uint4*)ll;
    }
}

// ---------------- depthwise causal conv (K=4) + silu — both dirs ----------------
__global__ void conv_silu_k(const float* __restrict__ x,
                            const float* __restrict__ wf, const float* __restrict__ bf,
                            const float* __restrict__ wb, const float* __restrict__ bbias,
                            float* __restrict__ xc)
{
    int t   = blockIdx.x * blockDim.x + threadIdx.x;
    int bdd = blockIdx.y;
    int dir = bdd >> 9;
    int bd  = bdd & 511;
    int d   = bd & 255;
    const float* w  = dir ? wb : wf;
    const float* bi = dir ? bbias : bf;
    const float* xp = x + (size_t)bd*LSEQ;
    float acc = bi[d];
    #pragma unroll
    for (int k = 0; k < 4; k++) {
        int s = t - 3 + k;
        if (s >= 0) {
            int ph = dir ? (LSEQ-1-s) : s;
            acc += w[d*4+k] * xp[ph];
        }
    }
    xc[(size_t)bdd*LSEQ + t] = acc * sigmoidf_(acc);
}

// ---------------- fp32 SGEMM (xproj / dtproj), per-dir weight select ----------------
enum { EP_NONE=0, EP_SPBIAS=1 };

template<int EP>
__global__ void __launch_bounds__(256) sgemm_k(
    const float* __restrict__ A0, const float* __restrict__ A1, int lda,
    const float* __restrict__ B, int ldb, long long bStride,
    float* __restrict__ C, int ldc, long long cStride,
    int M, int Kdim,
    const float* __restrict__ bias0, const float* __restrict__ bias1)
{
    __shared__ float As[8][128];
    __shared__ float Bs[8][128];
    int zb = blockIdx.z;
    int dir = zb >> 1;
    const float* A = dir ? A1 : A0;
    const float* bias = dir ? bias1 : bias0;
    B += (size_t)zb * bStride;
    C += (size_t)zb * cStride;

    int m0 = blockIdx.y * 128;
    int n0 = blockIdx.x * 128;
    int tid = threadIdx.x;
    int ar  = tid >> 1, ac = (tid & 1) << 2;
    int brr = tid >> 5, bc = (tid & 31) << 2;
    int mt0 = (tid >> 4) << 2, nt0 = (tid & 15) << 2;

    unsigned long long acc[8][4];
    #pragma unroll
    for (int i = 0; i < 8; i++)
        #pragma unroll
        for (int j = 0; j < 4; j++) acc[i][j] = 0ull;

    for (int k0 = 0; k0 < Kdim; k0 += 8) {
        float4 a4 = make_float4(0.f,0.f,0.f,0.f);
        int arow = m0 + ar;
        if (arow < M) a4 = *(const float4*)(A + (size_t)arow*lda + (k0 + ac));
        As[ac+0][ar] = a4.x; As[ac+1][ar] = a4.y; As[ac+2][ar] = a4.z; As[ac+3][ar] = a4.w;
        float4 b4 = *(const float4*)(B + (size_t)(k0 + brr)*ldb + (n0 + bc));
        *(float4*)&Bs[brr][bc] = b4;
        __syncthreads();
        #pragma unroll
        for (int kk = 0; kk < 8; kk++) {
            float4 aL = *(const float4*)&As[kk][mt0];
            float4 aH = *(const float4*)&As[kk][mt0+64];
            float av[8] = {aL.x,aL.y,aL.z,aL.w,aH.x,aH.y,aH.z,aH.w};
            unsigned long long b2[4];
            const unsigned long long* bpL = (const unsigned long long*)&Bs[kk][nt0];
            const unsigned long long* bpH = (const unsigned long long*)&Bs[kk][nt0+64];
            b2[0] = bpL[0]; b2[1] = bpL[1]; b2[2] = bpH[0]; b2[3] = bpH[1];
            #pragma unroll
            for (int i = 0; i < 8; i++) {
                unsigned long long a2;
                asm("mov.b64 %0, {%1, %1};" : "=l"(a2) : "f"(av[i]));
                #pragma unroll
                for (int j = 0; j < 4; j++)
                    asm("fma.rn.f32x2 %0, %1, %2, %0;" : "+l"(acc[i][j]) : "l"(a2), "l"(b2[j]));
            }
        }
        __syncthreads();
    }

    #pragma unroll
    for (int i = 0; i < 8; i++) {
        int m = m0 + ((i < 4) ? (mt0 + i) : (64 + mt0 + i - 4));
        if (m >= M) continue;
        float bv = (EP == EP_SPBIAS) ? bias[m] : 0.f;
        #pragma unroll
        for (int j = 0; j < 4; j++) {
            int n = n0 + ((j < 2) ? (nt0 + 2*j) : (64 + nt0 + 2*(j-2)));
            float2 v;
            asm("mov.b64 {%0, %1}, %2;" : "=f"(v.x), "=f"(v.y) : "l"(acc[i][j]));
            if (EP == EP_SPBIAS) { v.x = softplusf_(v.x + bv); v.y = softplusf_(v.y + bv); }
            *(float2*)(C + (size_t)m*ldc + n) = v;
        }
    }
}

// ---------------- chunked selective scan (both dirs in one launch) ----------------
__global__ void __launch_bounds__(256) scanA_k(
    const float* __restrict__ dt, const float* __restrict__ xc,
    const float* __restrict__ dbl,
    const float* __restrict__ A0, const float* __restrict__ A1,
    float* __restrict__ P, float* __restrict__ S)
{
    __shared__ float sdt[32][65], sx[32][65], sB[8][65];
    int chunk = blockIdx.x, zd = blockIdx.y, d0 = blockIdx.z * 32;
    int dir = zd >> 1, b = zd & 1;
    const float* Alog = dir ? A1 : A0;
    int tid = threadIdx.x;
    size_t base = ((size_t)(zd*DIMC + d0))*LSEQ + chunk*64;
    for (int i = tid; i < 2048; i += 256) {
        int r = i >> 6, c = i & 63;
        sdt[r][c] = dt[base + (size_t)r*LSEQ + c];
        sx [r][c] = xc[base + (size_t)r*LSEQ + c];
    }
    size_t bbase = ((size_t)(zd*32 + 16))*LSEQ + chunk*64;
    for (int i = tid; i < 512; i += 256) {
        int r = i >> 6, c = i & 63;
        sB[r][c] = dbl[bbase + (size_t)r*LSEQ + c];
    }
    __syncthreads();
    int dl = tid >> 3, n = tid & 7;
    float Aa = -__expf(Alog[(d0+dl)*8 + n]);
    float Pv = 1.f, Sv = 0.f;
    #pragma unroll 8
    for (int t = 0; t < 64; t++) {
        float dtv = sdt[dl][t];
        float dA  = __expf(dtv * Aa);
        Sv = Sv*dA + dtv * sx[dl][t] * sB[n][t];
        Pv *= dA;
    }
    size_t o = (size_t)dir*SCN_ + (((size_t)chunk*BATCH + b)*DIMC + d0+dl)*8 + n;
    P[o] = Pv; S[o] = Sv;
}

__global__ void scanB_k(const float* __restrict__ P, const float* __restrict__ S,
                        float* __restrict__ Hi)
{
    int gid = blockIdx.x * blockDim.x + threadIdx.x;
    int dir = gid >> 12, idx = gid & 4095;
    const float* Pd = P + (size_t)dir*SCN_;
    const float* Sd = S + (size_t)dir*SCN_;
    float* Hd = Hi + (size_t)dir*SCN_;
    float h = 0.f;
    for (int c0 = 0; c0 < 64; c0 += 8) {
        float p[8], s[8];
        #pragma unroll
        for (int j = 0; j < 8; j++) {
            size_t o = (size_t)(c0+j)*4096 + idx;
            p[j] = Pd[o]; s[j] = Sd[o];
        }
        #pragma unroll
        for (int j = 0; j < 8; j++) {
            Hd[(size_t)(c0+j)*4096 + idx] = h;
            h = h * p[j] + s[j];
        }
    }
}

__global__ void __launch_bounds__(256) scanC_k(
    const float* __restrict__ dt, const float* __restrict__ xc,
    const float* __restrict__ dbl,
    const float* __restrict__ A0, const float* __restrict__ A1,
    const float* __restrict__ Hi,
    const float* __restrict__ D0, const float* __restrict__ D1,
    const float* __restrict__ z, float* __restrict__ y)
{
    __shared__ float sdt[32][65], sx[32][65], sB[8][65], sC[8][65];
    __shared__ float sy[32][64];
    int chunk = blockIdx.x, zd = blockIdx.y, d0 = blockIdx.z * 32;
    int dir = zd >> 1, b = zd & 1;
    const float* Alog = dir ? A1 : A0;
    const float* Dp   = dir ? D1 : D0;
    int tid = threadIdx.x;
    size_t base = ((size_t)(zd*DIMC + d0))*LSEQ + chunk*64;
    for (int i = tid; i < 2048; i += 256) {
        int r = i >> 6, c = i & 63;
        sdt[r][c] = dt[base + (size_t)r*LSEQ + c];
        sx [r][c] = xc[base + (size_t)r*LSEQ + c];
    }
    size_t bbase = ((size_t)(zd*32 + 16))*LSEQ + chunk*64;
    size_t cbase = ((size_t)(zd*32 + 24))*LSEQ + chunk*64;
    for (int i = tid; i < 512; i += 256) {
        int r = i >> 6, c = i & 63;
        sB[r][c] = dbl[bbase + (size_t)r*LSEQ + c];
        sC[r][c] = dbl[cbase + (size_t)r*LSEQ + c];
    }
    __syncthreads();
    int dl = tid >> 3, n = tid & 7;
    float Aa = -__expf(Alog[(d0+dl)*8 + n]);
    float h = Hi[(size_t)dir*SCN_ + (((size_t)chunk*BATCH + b)*DIMC + d0+dl)*8 + n];
    for (int t = 0; t < 64; t++) {
        float dtv = sdt[dl][t];
        float dA  = __expf(dtv * Aa);
        h = h*dA + dtv * sx[dl][t] * sB[n][t];
        float yv = h * sC[n][t];
        yv += __shfl_down_sync(0xffffffffu, yv, 4);
        yv += __shfl_down_sync(0xffffffffu, yv, 2);
        yv += __shfl_down_sync(0xffffffffu, yv, 1);
        if (n == 0) sy[dl][t] = yv;
    }
    __syncthreads();
    float* yD = y + (size_t)dir * BATCH*DIMC*LSEQ;
    for (int i = tid; i < 2048; i += 256) {
        int r = i >> 6, c = i & 63;
        int tl = chunk*64 + c;
        int lp = dir ? (LSEQ-1-tl) : tl;
        size_t gi = ((size_t)(b*DIMC + d0 + r))*LSEQ + lp;
        float v = sy[r][c] + sx[r][c]*Dp[d0+r];
        float zz = z[gi];
        yD[gi] = v * zz * sigmoidf_(zz);
    }
}

// ---------------- rmsnorm 3 heads -> token-major fp16 ----------------
__global__ void __launch_bounds__(256) rms3_k(
    const float* __restrict__ yf, const float* __restrict__ yb,
    const float* __restrict__ w,
    __half* __restrict__ ynf)
{
    __shared__ float red[3][16][17];
    __shared__ float rfac[3][16];
    __shared__ uint32_t spk[16][132];
    int tid = threadIdx.x;
    int tok = tid & 15, sub = tid >> 4;
    int idx = blockIdx.x * 16 + tok;
    int b = idx >> 12, l = idx & (LSEQ-1);
    size_t base = (size_t)b*DIMC*LSEQ + l;

    float vf[16], vb[16], wv[16];
    float sa = 0.f, sf = 0.f, sb = 0.f;
    #pragma unroll
    for (int j = 0; j < 16; j++) {
        int c = sub*16 + j;
        float f = yf[base + (size_t)c*LSEQ];
        float bk = yb[base + (size_t)c*LSEQ];
        vf[j] = f; vb[j] = bk; wv[j] = w[c];
        float va = 0.5f*(f + bk);
        sa += va*va; sf += f*f; sb += bk*bk;
    }
    red[0][sub][tok] = sa; red[1][sub][tok] = sf; red[2][sub][tok] = sb;
    __syncthreads();
    if (tid < 48) {
        int hh = tid >> 4, tt = tid & 15;
        float S = 0.f;
        #pragma unroll
        for (int u = 0; u < 16; u++) S += red[hh][u][tt];
        rfac[hh][tt] = rsqrtf(S * (1.f/DIMC) + EPS_F);
    }
    __syncthreads();

    int tr = tid >> 4, seg = tid & 15;
    #pragma unroll 1
    for (int h = 0; h < 3; h++) {
        float r = rfac[h][tok];
        #pragma unroll
        for (int j2 = 0; j2 < 8; j2++) {
            int j = j2*2;
            float v0 = (h == 0) ? 0.5f*(vf[j] + vb[j])     : (h == 1) ? vf[j]   : vb[j];
            float v1 = (h == 0) ? 0.5f*(vf[j+1] + vb[j+1]) : (h == 1) ? vf[j+1] : vb[j+1];
            __half2 hv;
            hv.x = __float2half(v0 * r * wv[j]);
            hv.y = __float2half(v1 * r * wv[j+1]);
            spk[tok][sub*8 + j2] = *(uint32_t*)&hv;
        }
        __syncthreads();
        int idx2 = blockIdx.x*16 + tr;
        int b2 = idx2 >> 12, l2 = idx2 & (LSEQ-1);
        size_t obh = ((size_t)(h*2 + b2)*LSEQ + l2) * 256;
        #pragma unroll
        for (int it = 0; it < 2; it++) {
            int s2 = seg + it*16;     // 0..31, each 8 halves
            *(uint4*)(ynf + obh + s2*8) = *(uint4*)&spk[tr][s2*4];
        }
        __syncthreads();
    }
}

// ---------------- launch ----------------
extern "C" void kernel_launch(void* const* d_in, const int* in_sizes, int n_in,
                              void* d_out, int out_size)
{
    (void)in_sizes; (void)n_in; (void)out_size;
    const float* input0      = (const float*)d_in[0];
    const float* input1      = (const float*)d_in[1];
    const float* norm0_w     = (const float*)d_in[2];
    const float* norm0_b     = (const float*)d_in[3];
    const float* norm1_w     = (const float*)d_in[4];
    const float* norm1_b     = (const float*)d_in[5];
    const float* in_proj_w   = (const float*)d_in[6];
    const float* in_projz_w  = (const float*)d_in[7];
    const float* conv1d_w    = (const float*)d_in[8];
    const float* conv1d_bias = (const float*)d_in[9];
    const float* conv1db_w   = (const float*)d_in[10];
    const float* conv1db_bias= (const float*)d_in[11];
    const float* xproj_w     = (const float*)d_in[12];
    const float* xprojb_w    = (const float*)d_in[13];
    const float* dtproj_w    = (const float*)d_in[14];
    const float* dtproj_bias = (const float*)d_in[15];
    const float* dtprojb_w   = (const float*)d_in[16];
    const float* dtprojb_bias= (const float*)d_in[17];
    const float* A_log       = (const float*)d_in[18];
    const float* Ab_log      = (const float*)d_in[19];
    const float* D_p         = (const float*)d_in[20];
    const float* D_b         = (const float*)d_in[21];
    const float* rms_w       = (const float*)d_in[22];
    const float* out_proj_w  = (const float*)d_in[23];
    const float* conv3d_w    = (const float*)d_in[24];
    const float* conv3d_bias = (const float*)d_in[25];
    float* out = (float*)d_out;

    float *x_, *z_, *xc_, *dbl_, *dt_, *P_, *S_, *Hi_, *y_, *skipT;
    __nv_bfloat16 *s0h,*s0l,*s1h,*s1l;
    __half *ynf, *of_, *wopf, *wc3f;
    __nv_bfloat16 *wip_h,*wip_l,*wiz_h,*wiz_l;
    cudaGetSymbolAddress((void**)&x_,   g_x);
    cudaGetSymbolAddress((void**)&z_,   g_z);
    cudaGetSymbolAddress((void**)&xc_,  g_xc);
    cudaGetSymbolAddress((void**)&dbl_, g_dbl);
    cudaGetSymbolAddress((void**)&dt_,  g_dt);
    cudaGetSymbolAddress((void**)&P_,   g_P);
    cudaGetSymbolAddress((void**)&S_,   g_S);
    cudaGetSymbolAddress((void**)&Hi_,  g_Hi);
    cudaGetSymbolAddress((void**)&y_,   g_y);
    cudaGetSymbolAddress((void**)&skipT,g_skipT);
    cudaGetSymbolAddress((void**)&s0h,  g_s0h);
    cudaGetSymbolAddress((void**)&s0l,  g_s0l);
    cudaGetSymbolAddress((void**)&s1h,  g_s1h);
    cudaGetSymbolAddress((void**)&s1l,  g_s1l);
    cudaGetSymbolAddress((void**)&ynf,  g_ynf);
    cudaGetSymbolAddress((void**)&of_,  g_of);
    cudaGetSymbolAddress((void**)&wopf, g_wopf);
    cudaGetSymbolAddress((void**)&wc3f, g_wc3f);
    cudaGetSymbolAddress((void**)&wip_h, g_wip_h); cudaGetSymbolAddress((void**)&wip_l, g_wip_l);
    cudaGetSymbolAddress((void**)&wiz_h, g_wiz_h); cudaGetSymbolAddress((void**)&wiz_l, g_wiz_l);

    const int TCSMEM  = 2 * STG;    // 110592
    const int TCSMEMH = 2 * STGH;   // 55296
    cudaFuncSetAttribute(tcgemm_k, cudaFuncAttributeMaxDynamicSharedMemorySize, TCSMEM);
    cudaFuncSetAttribute(tcgemmH_k<EPH_SKIP>, cudaFuncAttributeMaxDynamicSharedMemorySize, TCSMEMH);
    cudaFuncSetAttribute(tcgemmH_k<EPH_BIAS>, cudaFuncAttributeMaxDynamicSharedMemorySize, TCSMEMH);

    const long long SB  = (long long)DIMC*LSEQ;
    const long long SB32= (long long)32*LSEQ;

    // 0) weight converts + skip transpose
    wsplit2_k<<<dim3(256,2), 256>>>(in_proj_w, in_projz_w,
                                    wip_h, wip_l, wiz_h, wiz_l);
    whalf2_k<<<dim3(1200,2), 256>>>(conv3d_w, out_proj_w, wc3f, wopf);
    xposeF_k<<<dim3(128,8,2), 256>>>(input0, skipT);

    // 1) layernorms -> token-major bf16 hi/lo
    ln_k<<<dim3(512,2), 256>>>(input0, input1, norm0_w, norm0_b, norm1_w, norm1_b,
                               s0h, s0l, s1h, s1l);

    // 2) in_proj + in_projz (3-pass bf16, merged) -> channel-major fp32
    tcgemm_k<<<dim3(4,32,4), 256, TCSMEM>>>(s0h, s0l, wip_h, wip_l,
                                            s1h, s1l, wiz_h, wiz_l, x_, z_);

    // 3) conv + silu, both dirs
    conv_silu_k<<<dim3(16,1024), 256>>>(x_, conv1d_w, conv1d_bias, conv1db_w, conv1db_bias,
                                        (float*)xc_);
    // 4) xproj, both dirs
    sgemm_k<EP_NONE><<<dim3(32,1,4), 256>>>(xproj_w, xprojb_w, 256,
                                            xc_, LSEQ, SB, dbl_, LSEQ, SB32,
                                            32, 256, nullptr, nullptr);
    // 5) dtproj + softplus, both dirs
    sgemm_k<EP_SPBIAS><<<dim3(32,2,4), 256>>>(dtproj_w, dtprojb_w, 16,
                                              dbl_, LSEQ, SB32, dt_, LSEQ, SB,
                                              256, 16, dtproj_bias, dtprojb_bias);
    // 6) chunked scan, both dirs
    scanA_k<<<dim3(64,4,8), 256>>>(dt_, xc_, dbl_, A_log, Ab_log, P_, S_);
    scanB_k<<<32, 256>>>(P_, S_, Hi_);
    scanC_k<<<dim3(64,4,8), 256>>>(dt_, xc_, dbl_, A_log, Ab_log, Hi_, D_p, D_b, z_, y_);

    // 7) rmsnorm 3 heads -> token-major fp16
    rms3_k<<<512, 256>>>(y_, y_ + (size_t)BATCH*DIMC*LSEQ, rms_w, ynf);

    // 8) out_proj (+skip) (1-pass fp16) -> token-major fp16 o
    tcgemmH_k<EPH_SKIP><<<dim3(4,32,6), 256, TCSMEMH>>>(ynf, wopf, 256,
                                                        nullptr, nullptr, skipT, of_);

    // 9) conv3d (1-pass fp16, +bias) -> final output (channel-major fp32)
    tcgemmH_k<EPH_BIAS><<<dim3(19,32,6), 256, TCSMEMH>>>(of_, wc3f, 1200,
                                                         out, conv3d_bias, nullptr, nullptr);
}

// round 16
// speedup vs baseline: 2.1525x; 1.0461x over previous
#include <cuda_runtime.h>
#include <cuda_bf16.h>
#include <cuda_fp16.h>
#include <cstdint>
#include <math.h>

#define LSEQ 4096
#define BATCH 2
#define DIMC 256
#define EPS_F 1e-5f
#define SCN_ (64*BATCH*DIMC*8)

// ---------------- scratch (device globals) ----------------
__device__ float g_xz  [4*DIMC*LSEQ];                 // slabs: x(b0),x(b1),z(b0),z(b1)
__device__ float g_xc  [2][BATCH*DIMC*LSEQ];
__device__ float g_dbl [2][BATCH*32*LSEQ];
__device__ float g_dt  [2][BATCH*DIMC*LSEQ];
__device__ float g_P   [2][SCN_];
__device__ float g_S   [2][SCN_];
__device__ float g_Hi  [2][SCN_];
__device__ float g_y   [2][BATCH*DIMC*LSEQ];
__device__ float g_skipT[BATCH*LSEQ*DIMC];

__device__ __half g_snf[4*LSEQ*DIMC];                 // ln out: slabs (which*2+b), fp16
__device__ __half g_ynf[6*LSEQ*DIMC];                 // rmsnorm out, fp16
__device__ __half g_of [6*LSEQ*DIMC];                 // out_proj(+skip) out, fp16
__device__ __half g_wipzf[2*DIMC*DIMC];               // in_proj / in_projz weights, fp16
__device__ __half g_wopf[DIMC*DIMC];                  // out_proj weight, fp16
__device__ __half g_wc3f[1200*DIMC];                  // conv3d weight, fp16

__device__ __forceinline__ float sigmoidf_(float x){ return 1.f/(1.f+__expf(-x)); }
__device__ __forceinline__ float softplusf_(float x){ return x>20.f ? x : log1pf(__expf(x)); }

__device__ __forceinline__ uint32_t smem_u32(const void* p) {
    uint32_t a;
    asm("{ .reg .u64 t; cvta.to.shared.u64 t, %1; cvt.u32.u64 %0, t; }" : "=r"(a) : "l"(p));
    return a;
}
__device__ __forceinline__ void ldmx4(uint32_t* r, uint32_t addr) {
    asm volatile("ldmatrix.sync.aligned.m8n8.x4.shared.b16 {%0,%1,%2,%3}, [%4];"
        : "=r"(r[0]),"=r"(r[1]),"=r"(r[2]),"=r"(r[3]) : "r"(addr));
}
__device__ __forceinline__ void mma16816h(float* d, const uint32_t* a, uint32_t b0, uint32_t b1) {
    asm volatile("mma.sync.aligned.m16n8k16.row.col.f32.f16.f16.f32 "
        "{%0,%1,%2,%3}, {%4,%5,%6,%7}, {%8,%9}, {%0,%1,%2,%3};"
        : "+f"(d[0]),"+f"(d[1]),"+f"(d[2]),"+f"(d[3])
        : "r"(a[0]),"r"(a[1]),"r"(a[2]),"r"(a[3]), "r"(b0),"r"(b1));
}
__device__ __forceinline__ void cp16(uint32_t dst, const void* src, int sz) {
    asm volatile("cp.async.cg.shared.global [%0], [%1], 16, %2;"
        :: "r"(dst), "l"(__cvta_generic_to_global(src)), "r"(sz) : "memory");
}

#define TILE_A  18432
#define TILE_BB 9216
#define EPH_SKIP  0
#define EPH_BIAS  1
#define EPH_XPOSE 2
#define STGH (TILE_A + TILE_BB)   // 27648

// ---------------- single-pass fp16 GEMM (all tensor-core GEMMs) ----------------
// D[128 tok, 64 ch] = A[tok,256] * W[ch,256]^T. 8 warps (mw x nw), 2 CTAs/SM.
// EPH_XPOSE: z = which*2+b; W selected by which; channel-major fp32 out.
// EPH_SKIP : + fp32 skip (token-major), fp16 token-major out.
// EPH_BIAS : + bias, channel-major fp32 out.
template<int EPH>
__global__ void __launch_bounds__(256, 2) tcgemmH_k(
    const __half* __restrict__ A, const __half* __restrict__ W, int bRows,
    float* __restrict__ outF, const float* __restrict__ bias,
    const float* __restrict__ skipT, __half* __restrict__ Of)
{
    extern __shared__ char smem[];
    const int tid = threadIdx.x, lane = tid & 31, warp = tid >> 5;
    const int mw = warp & 3, nw = warp >> 2;
    const int n0 = blockIdx.x * 64, tl0 = blockIdx.y * 128, zb = blockIdx.z;
    const long long t0 = (long long)zb * LSEQ + tl0;
    const __half* Wp = (EPH == EPH_XPOSE) ? (W + (size_t)(zb >> 1) * 65536) : W;

    float acc[2][4][4];
    #pragma unroll
    for (int i = 0; i < 2; i++)
        #pragma unroll
        for (int j = 0; j < 4; j++)
            #pragma unroll
            for (int c = 0; c < 4; c++) acc[i][j][c] = 0.f;

    const uint32_t sbase = smem_u32(smem);
    const int a_row  = (lane & 7) + ((lane >> 3) & 1) * 8;
    const int a_kadd = (lane >> 4) * 8;
    const int b_row  = (lane & 7) + (lane >> 4) * 8;
    const int b_kadd = ((lane >> 3) & 1) * 8;
    const uint32_t aoff = sbase + 0      + (uint32_t)((mw*32 + a_row)*72 + a_kadd) * 2;
    const uint32_t boff = sbase + TILE_A + (uint32_t)((nw*32 + b_row)*72 + b_kadd) * 2;

    const int lrow = tid >> 3, lc8 = (tid & 7) * 8;

    auto load_chunk = [&](int kc, int stage) {
        const int kofs = kc * 64;
        const uint32_t sb0 = sbase + stage * STGH;
        #pragma unroll
        for (int it = 0; it < 4; it++) {
            int row = lrow + it * 32;
            cp16(sb0 + (uint32_t)(row * 72 + lc8) * 2, A + (t0 + row) * 256 + kofs + lc8, 16);
        }
        #pragma unroll
        for (int it = 0; it < 2; it++) {
            int row = lrow + it * 32;
            int brow = n0 + row;
            int ok = (brow < bRows) ? 16 : 0;
            if (brow >= bRows) brow = bRows - 1;
            cp16(sb0 + TILE_A + (uint32_t)(row * 72 + lc8) * 2,
                 Wp + (size_t)brow * 256 + kofs + lc8, ok);
        }
    };

    auto compute = [&](int stage) {
        const uint32_t sadd = (uint32_t)stage * STGH;
        #pragma unroll
        for (int ks = 0; ks < 4; ks++) {
            const uint32_t k2 = (uint32_t)(ks * 16) * 2;
            uint32_t aF[2][4], bF[2][4];
            #pragma unroll
            for (int i = 0; i < 2; i++) ldmx4(aF[i], aoff + sadd + i*16*144 + k2);
            #pragma unroll
            for (int g = 0; g < 2; g++) ldmx4(bF[g], boff + sadd + g*16*144 + k2);
            #pragma unroll
            for (int i = 0; i < 2; i++)
                #pragma unroll
                for (int g = 0; g < 2; g++)
                    #pragma unroll
                    for (int p = 0; p < 2; p++)
                        mma16816h(acc[i][g*2+p], aF[i], bF[g][2*p], bF[g][2*p+1]);
        }
    };

    load_chunk(0, 0);
    asm volatile("cp.async.commit_group;" ::: "memory");
    for (int kc = 0; kc < 4; kc++) {
        if (kc < 3) {
            load_chunk(kc + 1, (kc + 1) & 1);
            asm volatile("cp.async.commit_group;" ::: "memory");
            asm volatile("cp.async.wait_group 1;" ::: "memory");
        } else {
            asm volatile("cp.async.wait_group 0;" ::: "memory");
        }
        __syncthreads();
        compute(kc & 1);
        __syncthreads();
    }

    if (EPH == EPH_SKIP) {
        #pragma unroll
        for (int i = 0; i < 2; i++)
            #pragma unroll
            for (int rr = 0; rr < 2; rr++) {
                int tok = tl0 + mw*32 + i*16 + (lane >> 2) + rr*8;
                size_t orow = ((size_t)zb * LSEQ + tok) * 256;
                size_t srow = ((size_t)(zb & 1) * LSEQ + tok) * 256;
                #pragma unroll
                for (int j4 = 0; j4 < 4; j4++) {
                    int n = n0 + nw*32 + j4*8 + 2*(lane & 3);
                    float2 sk = *(const float2*)(skipT + srow + n);
                    __half2 hv;
                    hv.x = __float2half(acc[i][j4][rr*2+0] + sk.x);
                    hv.y = __float2half(acc[i][j4][rr*2+1] + sk.y);
                    *(__half2*)(Of + orow + n) = hv;
                }
            }
    } else {
        // channel-major fp32 (+bias for EPH_BIAS) via smem transpose
        float* sbuf = (float*)smem;
        __syncthreads();
        #pragma unroll
        for (int i = 0; i < 2; i++)
            #pragma unroll
            for (int j4 = 0; j4 < 4; j4++)
                #pragma unroll
                for (int rr = 0; rr < 2; rr++) {
                    int tok = mw*32 + i*16 + (lane >> 2) + rr*8;
                    int nl = nw*32 + j4*8 + 2*(lane & 3);
                    sbuf[nl*132 + tok]     = acc[i][j4][rr*2+0];
                    sbuf[(nl+1)*132 + tok] = acc[i][j4][rr*2+1];
                }
        __syncthreads();
        int row = tid >> 2;
        int n = n0 + row;
        if (n < bRows) {
            float bv = (EPH == EPH_BIAS) ? bias[n] : 0.f;
            const float* srcr = sbuf + row*132;
            float* dstr = outF + ((size_t)zb * bRows + n) * LSEQ + tl0;
            int c0 = (tid & 3) * 4;
            #pragma unroll
            for (int q = 0; q < 8; q++) {
                int col = c0 + q*16;
                float4 v = *(const float4*)(srcr + col);
                v.x += bv; v.y += bv; v.z += bv; v.w += bv;
                *(float4*)(dstr + col) = v;
            }
        }
    }
}

// ---------------- fused fp16 weight converts (4 segments) ----------------
__global__ void whalf4_k(const float* __restrict__ w0, const float* __restrict__ w1,
                         const float* __restrict__ w2, const float* __restrict__ w3,
                         __half* __restrict__ o0, __half* __restrict__ o1,
                         __half* __restrict__ o2, __half* __restrict__ o3)
{
    int seg = blockIdx.y;
    const float* w = seg==0?w0 : seg==1?w1 : seg==2?w2 : w3;
    __half* o = seg==0?o0 : seg==1?o1 : seg==2?o2 : o3;
    int n = (seg < 3) ? 65536 : 307200;
    int i = blockIdx.x * blockDim.x + threadIdx.x;
    if (i < n) o[i] = __float2half(w[i]);
}

// ---------------- transpose input0 -> token-major fp32 ----------------
__global__ void xposeF_k(const float* __restrict__ in, float* __restrict__ out)
{
    __shared__ float t[32][33];
    int b = blockIdx.z;
    int tok0 = blockIdx.x * 32, ch0 = blockIdx.y * 32;
    int lx = threadIdx.x & 31, ly = threadIdx.x >> 5;
    #pragma unroll
    for (int i = 0; i < 4; i++) {
        int ch = ch0 + ly + i*8;
        t[lx][ly + i*8] = in[((size_t)b*256 + ch)*LSEQ + tok0 + lx];
    }
    __syncthreads();
    #pragma unroll
    for (int i = 0; i < 4; i++) {
        int tok = tok0 + ly + i*8;
        out[((size_t)b*LSEQ + tok)*256 + ch0 + lx] = t[ly + i*8][lx];
    }
}

// ---------------- layernorm -> token-major fp16 (16 tokens x 16-way split / block) ----------------
__global__ void __launch_bounds__(256) ln_k(
    const float* __restrict__ in0, const float* __restrict__ in1,
    const float* __restrict__ w0, const float* __restrict__ b0,
    const float* __restrict__ w1, const float* __restrict__ b1,
    __half* __restrict__ snf)
{
    __shared__ float ssum[16][17], s2sum[16][17];
    __shared__ float mrs[2][16];
    __shared__ uint32_t spk[16][132];
    int which = blockIdx.y;
    const float* in = which ? in1 : in0;
    const float* w  = which ? w1  : w0;
    const float* bb = which ? b1  : b0;

    int tid = threadIdx.x;
    int tok = tid & 15, sub = tid >> 4;
    int idx = blockIdx.x * 16 + tok;
    int b = idx >> 12, l = idx & (LSEQ-1);
    const float* p = in + (size_t)b*DIMC*LSEQ + l;

    float vals[16];
    float s = 0.f, s2 = 0.f;
    #pragma unroll
    for (int j = 0; j < 16; j++) {
        float v = p[(size_t)(sub*16 + j)*LSEQ];
        vals[j] = v; s += v; s2 += v*v;
    }
    ssum[sub][tok] = s; s2sum[sub][tok] = s2;
    __syncthreads();
    if (tid < 16) {
        float S = 0.f, S2 = 0.f;
        #pragma unroll
        for (int u = 0; u < 16; u++) { S += ssum[u][tid]; S2 += s2sum[u][tid]; }
        float mean = S * (1.f/DIMC);
        float var  = S2 * (1.f/DIMC) - mean*mean;
        mrs[0][tid] = mean; mrs[1][tid] = rsqrtf(var + EPS_F);
    }
    __syncthreads();
    float mean = mrs[0][tok], rstd = mrs[1][tok];
    #pragma unroll
    for (int j2 = 0; j2 < 8; j2++) {
        int c = sub*16 + j2*2;
        __half2 hv;
        hv.x = __float2half((vals[j2*2]   - mean) * rstd * w[c]   + bb[c]);
        hv.y = __float2half((vals[j2*2+1] - mean) * rstd * w[c+1] + bb[c+1]);
        spk[tok][sub*8 + j2] = *(uint32_t*)&hv;
    }
    __syncthreads();
    int tr = tid >> 4, seg = tid & 15;
    int idx2 = blockIdx.x*16 + tr;
    int b2 = idx2 >> 12, l2 = idx2 & (LSEQ-1);
    size_t obh = ((size_t)(which*2 + b2)*LSEQ + l2) * 256;
    #pragma unroll
    for (int it = 0; it < 2; it++) {
        int s2i = seg + it*16;
        *(uint4*)(snf + obh + s2i*8) = *(uint4*)&spk[tr][s2i*4];
    }
}

// ---------------- depthwise causal conv (K=4) + silu — both dirs ----------------
__global__ void conv_silu_k(const float* __restrict__ x,
                            const float* __restrict__ wf, const float* __restrict__ bf,
                            const float* __restrict__ wb, const float* __restrict__ bbias,
                            float* __restrict__ xc)
{
    int t   = blockIdx.x * blockDim.x + threadIdx.x;
    int bdd = blockIdx.y;
    int dir = bdd >> 9;
    int bd  = bdd & 511;
    int d   = bd & 255;
    const float* w  = dir ? wb : wf;
    const float* bi = dir ? bbias : bf;
    const float* xp = x + (size_t)bd*LSEQ;
    float acc = bi[d];
    #pragma unroll
    for (int k = 0; k < 4; k++) {
        int s = t - 3 + k;
        if (s >= 0) {
            int ph = dir ? (LSEQ-1-s) : s;
            acc += w[d*4+k] * xp[ph];
        }
    }
    xc[(size_t)bdd*LSEQ + t] = acc * sigmoidf_(acc);
}

// ---------------- fp32 SGEMM (xproj / dtproj), per-dir weight select ----------------
enum { EP_NONE=0, EP_SPBIAS=1 };

template<int EP>
__global__ void __launch_bounds__(256) sgemm_k(
    const float* __restrict__ A0, const float* __restrict__ A1, int lda,
    const float* __restrict__ B, int ldb, long long bStride,
    float* __restrict__ C, int ldc, long long cStride,
    int M, int Kdim,
    const float* __restrict__ bias0, const float* __restrict__ bias1)
{
    __shared__ float As[8][128];
    __shared__ float Bs[8][128];
    int zb = blockIdx.z;
    int dir = zb >> 1;
    const float* A = dir ? A1 : A0;
    const float* bias = dir ? bias1 : bias0;
    B += (size_t)zb * bStride;
    C += (size_t)zb * cStride;

    int m0 = blockIdx.y * 128;
    int n0 = blockIdx.x * 128;
    int tid = threadIdx.x;
    int ar  = tid >> 1, ac = (tid & 1) << 2;
    int brr = tid >> 5, bc = (tid & 31) << 2;
    int mt0 = (tid >> 4) << 2, nt0 = (tid & 15) << 2;

    unsigned long long acc[8][4];
    #pragma unroll
    for (int i = 0; i < 8; i++)
        #pragma unroll
        for (int j = 0; j < 4; j++) acc[i][j] = 0ull;

    for (int k0 = 0; k0 < Kdim; k0 += 8) {
        float4 a4 = make_float4(0.f,0.f,0.f,0.f);
        int arow = m0 + ar;
        if (arow < M) a4 = *(const float4*)(A + (size_t)arow*lda + (k0 + ac));
        As[ac+0][ar] = a4.x; As[ac+1][ar] = a4.y; As[ac+2][ar] = a4.z; As[ac+3][ar] = a4.w;
        float4 b4 = *(const float4*)(B + (size_t)(k0 + brr)*ldb + (n0 + bc));
        *(float4*)&Bs[brr][bc] = b4;
        __syncthreads();
        #pragma unroll
        for (int kk = 0; kk < 8; kk++) {
            float4 aL = *(const float4*)&As[kk][mt0];
            float4 aH = *(const float4*)&As[kk][mt0+64];
            float av[8] = {aL.x,aL.y,aL.z,aL.w,aH.x,aH.y,aH.z,aH.w};
            unsigned long long b2[4];
            const unsigned long long* bpL = (const unsigned long long*)&Bs[kk][nt0];
            const unsigned long long* bpH = (const unsigned long long*)&Bs[kk][nt0+64];
            b2[0] = bpL[0]; b2[1] = bpL[1]; b2[2] = bpH[0]; b2[3] = bpH[1];
            #pragma unroll
            for (int i = 0; i < 8; i++) {
                unsigned long long a2;
                asm("mov.b64 %0, {%1, %1};" : "=l"(a2) : "f"(av[i]));
                #pragma unroll
                for (int j = 0; j < 4; j++)
                    asm("fma.rn.f32x2 %0, %1, %2, %0;" : "+l"(acc[i][j]) : "l"(a2), "l"(b2[j]));
            }
        }
        __syncthreads();
    }

    #pragma unroll
    for (int i = 0; i < 8; i++) {
        int m = m0 + ((i < 4) ? (mt0 + i) : (64 + mt0 + i - 4));
        if (m >= M) continue;
        float bv = (EP == EP_SPBIAS) ? bias[m] : 0.f;
        #pragma unroll
        for (int j = 0; j < 4; j++) {
            int n = n0 + ((j < 2) ? (nt0 + 2*j) : (64 + nt0 + 2*(j-2)));
            float2 v;
            asm("mov.b64 {%0, %1}, %2;" : "=f"(v.x), "=f"(v.y) : "l"(acc[i][j]));
            if (EP == EP_SPBIAS) { v.x = softplusf_(v.x + bv); v.y = softplusf_(v.y + bv); }
            *(float2*)(C + (size_t)m*ldc + n) = v;
        }
    }
}

// ---------------- chunked selective scan (both dirs in one launch) ----------------
__global__ void __launch_bounds__(256) scanA_k(
    const float* __restrict__ dt, const float* __restrict__ xc,
    const float* __restrict__ dbl,
    const float* __restrict__ A0, const float* __restrict__ A1,
    float* __restrict__ P, float* __restrict__ S)
{
    __shared__ float sdt[32][65], sx[32][65], sB[8][65];
    int chunk = blockIdx.x, zd = blockIdx.y, d0 = blockIdx.z * 32;
    int dir = zd >> 1, b = zd & 1;
    const float* Alog = dir ? A1 : A0;
    int tid = threadIdx.x;
    size_t base = ((size_t)(zd*DIMC + d0))*LSEQ + chunk*64;
    for (int i = tid; i < 2048; i += 256) {
        int r = i >> 6, c = i & 63;
        sdt[r][c] = dt[base + (size_t)r*LSEQ + c];
        sx [r][c] = xc[base + (size_t)r*LSEQ + c];
    }
    size_t bbase = ((size_t)(zd*32 + 16))*LSEQ + chunk*64;
    for (int i = tid; i < 512; i += 256) {
        int r = i >> 6, c = i & 63;
        sB[r][c] = dbl[bbase + (size_t)r*LSEQ + c];
    }
    __syncthreads();
    int dl = tid >> 3, n = tid & 7;
    float Aa = -__expf(Alog[(d0+dl)*8 + n]);
    float Pv = 1.f, Sv = 0.f;
    #pragma unroll 8
    for (int t = 0; t < 64; t++) {
        float dtv = sdt[dl][t];
        float dA  = __expf(dtv * Aa);
        Sv = Sv*dA + dtv * sx[dl][t] * sB[n][t];
        Pv *= dA;
    }
    size_t o = (size_t)dir*SCN_ + (((size_t)chunk*BATCH + b)*DIMC + d0+dl)*8 + n;
    P[o] = Pv; S[o] = Sv;
}

__global__ void scanB_k(const float* __restrict__ P, const float* __restrict__ S,
                        float* __restrict__ Hi)
{
    int gid = blockIdx.x * blockDim.x + threadIdx.x;
    int dir = gid >> 12, idx = gid & 4095;
    const float* Pd = P + (size_t)dir*SCN_;
    const float* Sd = S + (size_t)dir*SCN_;
    float* Hd = Hi + (size_t)dir*SCN_;
    float h = 0.f;
    for (int c0 = 0; c0 < 64; c0 += 8) {
        float p[8], s[8];
        #pragma unroll
        for (int j = 0; j < 8; j++) {
            size_t o = (size_t)(c0+j)*4096 + idx;
            p[j] = Pd[o]; s[j] = Sd[o];
        }
        #pragma unroll
        for (int j = 0; j < 8; j++) {
            Hd[(size_t)(c0+j)*4096 + idx] = h;
            h = h * p[j] + s[j];
        }
    }
}

__global__ void __launch_bounds__(256) scanC_k(
    const float* __restrict__ dt, const float* __restrict__ xc,
    const float* __restrict__ dbl,
    const float* __restrict__ A0, const float* __restrict__ A1,
    const float* __restrict__ Hi,
    const float* __restrict__ D0, const float* __restrict__ D1,
    const float* __restrict__ z, float* __restrict__ y)
{
    __shared__ float sdt[32][65], sx[32][65], sB[8][65], sC[8][65];
    __shared__ float sy[32][64];
    int chunk = blockIdx.x, zd = blockIdx.y, d0 = blockIdx.z * 32;
    int dir = zd >> 1, b = zd & 1;
    const float* Alog = dir ? A1 : A0;
    const float* Dp   = dir ? D1 : D0;
    int tid = threadIdx.x;
    size_t base = ((size_t)(zd*DIMC + d0))*LSEQ + chunk*64;
    for (int i = tid; i < 2048; i += 256) {
        int r = i >> 6, c = i & 63;
        sdt[r][c] = dt[base + (size_t)r*LSEQ + c];
        sx [r][c] = xc[base + (size_t)r*LSEQ + c];
    }
    size_t bbase = ((size_t)(zd*32 + 16))*LSEQ + chunk*64;
    size_t cbase = ((size_t)(zd*32 + 24))*LSEQ + chunk*64;
    for (int i = tid; i < 512; i += 256) {
        int r = i >> 6, c = i & 63;
        sB[r][c] = dbl[bbase + (size_t)r*LSEQ + c];
        sC[r][c] = dbl[cbase + (size_t)r*LSEQ + c];
    }
    __syncthreads();
    int dl = tid >> 3, n = tid & 7;
    float Aa = -__expf(Alog[(d0+dl)*8 + n]);
    float h = Hi[(size_t)dir*SCN_ + (((size_t)chunk*BATCH + b)*DIMC + d0+dl)*8 + n];
    for (int t = 0; t < 64; t++) {
        float dtv = sdt[dl][t];
        float dA  = __expf(dtv * Aa);
        h = h*dA + dtv * sx[dl][t] * sB[n][t];
        float yv = h * sC[n][t];
        yv += __shfl_down_sync(0xffffffffu, yv, 4);
        yv += __shfl_down_sync(0xffffffffu, yv, 2);
        yv += __shfl_down_sync(0xffffffffu, yv, 1);
        if (n == 0) sy[dl][t] = yv;
    }
    __syncthreads();
    float* yD = y + (size_t)dir * BATCH*DIMC*LSEQ;
    for (int i = tid; i < 2048; i += 256) {
        int r = i >> 6, c = i & 63;
        int tl = chunk*64 + c;
        int lp = dir ? (LSEQ-1-tl) : tl;
        size_t gi = ((size_t)(b*DIMC + d0 + r))*LSEQ + lp;
        float v = sy[r][c] + sx[r][c]*Dp[d0+r];
        float zz = z[gi];
        yD[gi] = v * zz * sigmoidf_(zz);
    }
}

// ---------------- rmsnorm 3 heads -> token-major fp16 ----------------
__global__ void __launch_bounds__(256) rms3_k(
    const float* __restrict__ yf, const float* __restrict__ yb,
    const float* __restrict__ w,
    __half* __restrict__ ynf)
{
    __shared__ float red[3][16][17];
    __shared__ float rfac[3][16];
    __shared__ uint32_t spk[16][132];
    int tid = threadIdx.x;
    int tok = tid & 15, sub = tid >> 4;
    int idx = blockIdx.x * 16 + tok;
    int b = idx >> 12, l = idx & (LSEQ-1);
    size_t base = (size_t)b*DIMC*LSEQ + l;

    float vf[16], vb[16], wv[16];
    float sa = 0.f, sf = 0.f, sb = 0.f;
    #pragma unroll
    for (int j = 0; j < 16; j++) {
        int c = sub*16 + j;
        float f = yf[base + (size_t)c*LSEQ];
        float bk = yb[base + (size_t)c*LSEQ];
        vf[j] = f; vb[j] = bk; wv[j] = w[c];
        float va = 0.5f*(f + bk);
        sa += va*va; sf += f*f; sb += bk*bk;
    }
    red[0][sub][tok] = sa; red[1][sub][tok] = sf; red[2][sub][tok] = sb;
    __syncthreads();
    if (tid < 48) {
        int hh = tid >> 4, tt = tid & 15;
        float S = 0.f;
        #pragma unroll
        for (int u = 0; u < 16; u++) S += red[hh][u][tt];
        rfac[hh][tt] = rsqrtf(S * (1.f/DIMC) + EPS_F);
    }
    __syncthreads();

    int tr = tid >> 4, seg = tid & 15;
    #pragma unroll 1
    for (int h = 0; h < 3; h++) {
        float r = rfac[h][tok];
        #pragma unroll
        for (int j2 = 0; j2 < 8; j2++) {
            int j = j2*2;
            float v0 = (h == 0) ? 0.5f*(vf[j] + vb[j])     : (h == 1) ? vf[j]   : vb[j];
            float v1 = (h == 0) ? 0.5f*(vf[j+1] + vb[j+1]) : (h == 1) ? vf[j+1] : vb[j+1];
            __half2 hv;
            hv.x = __float2half(v0 * r * wv[j]);
            hv.y = __float2half(v1 * r * wv[j+1]);
            spk[tok][sub*8 + j2] = *(uint32_t*)&hv;
        }
        __syncthreads();
        int idx2 = blockIdx.x*16 + tr;
        int b2 = idx2 >> 12, l2 = idx2 & (LSEQ-1);
        size_t obh = ((size_t)(h*2 + b2)*LSEQ + l2) * 256;
        #pragma unroll
        for (int it = 0; it < 2; it++) {
            int s2 = seg + it*16;
            *(uint4*)(ynf + obh + s2*8) = *(uint4*)&spk[tr][s2*4];
        }
        __syncthreads();
    }
}

// ---------------- launch ----------------
extern "C" void kernel_launch(void* const* d_in, const int* in_sizes, int n_in,
                              void* d_out, int out_size)
{
    (void)in_sizes; (void)n_in; (void)out_size;
    const float* input0      = (const float*)d_in[0];
    const float* input1      = (const float*)d_in[1];
    const float* norm0_w     = (const float*)d_in[2];
    const float* norm0_b     = (const float*)d_in[3];
    const float* norm1_w     = (const float*)d_in[4];
    const float* norm1_b     = (const float*)d_in[5];
    const float* in_proj_w   = (const float*)d_in[6];
    const float* in_projz_w  = (const float*)d_in[7];
    const float* conv1d_w    = (const float*)d_in[8];
    const float* conv1d_bias = (const float*)d_in[9];
    const float* conv1db_w   = (const float*)d_in[10];
    const float* conv1db_bias= (const float*)d_in[11];
    const float* xproj_w     = (const float*)d_in[12];
    const float* xprojb_w    = (const float*)d_in[13];
    const float* dtproj_w    = (const float*)d_in[14];
    const float* dtproj_bias = (const float*)d_in[15];
    const float* dtprojb_w   = (const float*)d_in[16];
    const float* dtprojb_bias= (const float*)d_in[17];
    const float* A_log       = (const float*)d_in[18];
    const float* Ab_log      = (const float*)d_in[19];
    const float* D_p         = (const float*)d_in[20];
    const float* D_b         = (const float*)d_in[21];
    const float* rms_w       = (const float*)d_in[22];
    const float* out_proj_w  = (const float*)d_in[23];
    const float* conv3d_w    = (const float*)d_in[24];
    const float* conv3d_bias = (const float*)d_in[25];
    float* out = (float*)d_out;

    float *xz_, *xc_, *dbl_, *dt_, *P_, *S_, *Hi_, *y_, *skipT;
    __half *snf, *ynf, *of_, *wipzf, *wopf, *wc3f;
    cudaGetSymbolAddress((void**)&xz_,  g_xz);
    cudaGetSymbolAddress((void**)&xc_,  g_xc);
    cudaGetSymbolAddress((void**)&dbl_, g_dbl);
    cudaGetSymbolAddress((void**)&dt_,  g_dt);
    cudaGetSymbolAddress((void**)&P_,   g_P);
    cudaGetSymbolAddress((void**)&S_,   g_S);
    cudaGetSymbolAddress((void**)&Hi_,  g_Hi);
    cudaGetSymbolAddress((void**)&y_,   g_y);
    cudaGetSymbolAddress((void**)&skipT,g_skipT);
    cudaGetSymbolAddress((void**)&snf,  g_snf);
    cudaGetSymbolAddress((void**)&ynf,  g_ynf);
    cudaGetSymbolAddress((void**)&of_,  g_of);
    cudaGetSymbolAddress((void**)&wipzf,g_wipzf);
    cudaGetSymbolAddress((void**)&wopf, g_wopf);
    cudaGetSymbolAddress((void**)&wc3f, g_wc3f);

    float* x_ = xz_;
    float* z_ = xz_ + (size_t)2*DIMC*LSEQ;

    const int TCSMEMH = 2 * STGH;   // 55296
    cudaFuncSetAttribute(tcgemmH_k<EPH_XPOSE>, cudaFuncAttributeMaxDynamicSharedMemorySize, TCSMEMH);
    cudaFuncSetAttribute(tcgemmH_k<EPH_SKIP>,  cudaFuncAttributeMaxDynamicSharedMemorySize, TCSMEMH);
    cudaFuncSetAttribute(tcgemmH_k<EPH_BIAS>,  cudaFuncAttributeMaxDynamicSharedMemorySize, TCSMEMH);

    const long long SB  = (long long)DIMC*LSEQ;
    const long long SB32= (long long)32*LSEQ;

    // 0) weight converts (one launch) + skip transpose
    whalf4_k<<<dim3(1200,4), 256>>>(in_proj_w, in_projz_w, out_proj_w, conv3d_w,
                                    wipzf, wipzf + 65536, wopf, wc3f);
    xposeF_k<<<dim3(128,8,2), 256>>>(input0, skipT);

    // 1) layernorms -> token-major fp16 (slabs which*2+b)
    ln_k<<<dim3(512,2), 256>>>(input0, input1, norm0_w, norm0_b, norm1_w, norm1_b, snf);

    // 2) in_proj + in_projz (1-pass fp16, merged z=4) -> channel-major fp32 x|z
    tcgemmH_k<EPH_XPOSE><<<dim3(4,32,4), 256, TCSMEMH>>>(snf, wipzf, 256,
                                                         xz_, nullptr, nullptr, nullptr);

    // 3) conv + silu, both dirs
    conv_silu_k<<<dim3(16,1024), 256>>>(x_, conv1d_w, conv1d_bias, conv1db_w, conv1db_bias,
                                        (float*)xc_);
    // 4) xproj, both dirs
    sgemm_k<EP_NONE><<<dim3(32,1,4), 256>>>(xproj_w, xprojb_w, 256,
                                            xc_, LSEQ, SB, dbl_, LSEQ, SB32,
                                            32, 256, nullptr, nullptr);
    // 5) dtproj + softplus, both dirs
    sgemm_k<EP_SPBIAS><<<dim3(32,2,4), 256>>>(dtproj_w, dtprojb_w, 16,
                                              dbl_, LSEQ, SB32, dt_, LSEQ, SB,
                                              256, 16, dtproj_bias, dtprojb_bias);
    // 6) chunked scan, both dirs
    scanA_k<<<dim3(64,4,8), 256>>>(dt_, xc_, dbl_, A_log, Ab_log, P_, S_);
    scanB_k<<<32, 256>>>(P_, S_, Hi_);
    scanC_k<<<dim3(64,4,8), 256>>>(dt_, xc_, dbl_, A_log, Ab_log, Hi_, D_p, D_b, z_, y_);

    // 7) rmsnorm 3 heads -> token-major fp16
    rms3_k<<<512, 256>>>(y_, y_ + (size_t)BATCH*DIMC*LSEQ, rms_w, ynf);

    // 8) out_proj (+skip) (1-pass fp16) -> token-major fp16 o
    tcgemmH_k<EPH_SKIP><<<dim3(4,32,6), 256, TCSMEMH>>>(ynf, wopf, 256,
                                                        nullptr, nullptr, skipT, of_);

    // 9) conv3d (1-pass fp16, +bias) -> final output (channel-major fp32)
    tcgemmH_k<EPH_BIAS><<<dim3(19,32,6), 256, TCSMEMH>>>(of_, wc3f, 1200,
                                                         out, conv3d_bias, nullptr, nullptr);
}

// round 17
// speedup vs baseline: 2.1715x; 1.0088x over previous
#include <cuda_runtime.h>
#include <cuda_bf16.h>
#include <cuda_fp16.h>
#include <cstdint>
#include <math.h>

#define LSEQ 4096
#define BATCH 2
#define DIMC 256
#define EPS_F 1e-5f
#define SCN_ (64*BATCH*DIMC*8)

// ---------------- scratch (device globals) ----------------
__device__ float g_xz  [4*DIMC*LSEQ];                 // slabs: x(b0),x(b1),z(b0),z(b1)
__device__ float g_xc  [2][BATCH*DIMC*LSEQ];
__device__ float g_dbl [2][BATCH*32*LSEQ];
__device__ __half g_dt [2][BATCH*DIMC*LSEQ];          // dt, fp16
__device__ float g_P   [2][SCN_];
__device__ float g_S   [2][SCN_];
__device__ float g_Hi  [2][SCN_];
__device__ float g_y   [2][BATCH*DIMC*LSEQ];
__device__ float g_skipT[BATCH*LSEQ*DIMC];

__device__ __half g_snf[4*LSEQ*DIMC];                 // ln out: slabs (which*2+b), fp16
__device__ __half g_ynf[6*LSEQ*DIMC];                 // rmsnorm out, fp16
__device__ __half g_of [6*LSEQ*DIMC];                 // out_proj(+skip) out, fp16
__device__ __half g_wipzf[2*DIMC*DIMC];               // in_proj / in_projz weights, fp16
__device__ __half g_wopf[DIMC*DIMC];                  // out_proj weight, fp16
__device__ __half g_wc3f[1200*DIMC];                  // conv3d weight, fp16

__device__ __forceinline__ float sigmoidf_(float x){ return 1.f/(1.f+__expf(-x)); }
__device__ __forceinline__ float softplusf_(float x){ return x>20.f ? x : log1pf(__expf(x)); }

__device__ __forceinline__ uint32_t smem_u32(const void* p) {
    uint32_t a;
    asm("{ .reg .u64 t; cvta.to.shared.u64 t, %1; cvt.u32.u64 %0, t; }" : "=r"(a) : "l"(p));
    return a;
}
__device__ __forceinline__ void ldmx4(uint32_t* r, uint32_t addr) {
    asm volatile("ldmatrix.sync.aligned.m8n8.x4.shared.b16 {%0,%1,%2,%3}, [%4];"
        : "=r"(r[0]),"=r"(r[1]),"=r"(r[2]),"=r"(r[3]) : "r"(addr));
}
__device__ __forceinline__ void mma16816h(float* d, const uint32_t* a, uint32_t b0, uint32_t b1) {
    asm volatile("mma.sync.aligned.m16n8k16.row.col.f32.f16.f16.f32 "
        "{%0,%1,%2,%3}, {%4,%5,%6,%7}, {%8,%9}, {%0,%1,%2,%3};"
        : "+f"(d[0]),"+f"(d[1]),"+f"(d[2]),"+f"(d[3])
        : "r"(a[0]),"r"(a[1]),"r"(a[2]),"r"(a[3]), "r"(b0),"r"(b1));
}
__device__ __forceinline__ void cp16(uint32_t dst, const void* src, int sz) {
    asm volatile("cp.async.cg.shared.global [%0], [%1], 16, %2;"
        :: "r"(dst), "l"(__cvta_generic_to_global(src)), "r"(sz) : "memory");
}

#define TILE_A  18432
#define TILE_BB 9216
#define EPH_SKIP  0
#define EPH_BIAS  1
#define EPH_XPOSE 2
#define STGH (TILE_A + TILE_BB)   // 27648; 3 stages = 82944

// ---------------- single-pass fp16 GEMM, 3-stage cp.async pipeline ----------------
// D[128 tok, 64 ch] = A[tok,256] * W[ch,256]^T. 8 warps (mw x nw), 2 CTAs/SM.
template<int EPH>
__global__ void __launch_bounds__(256, 2) tcgemmH_k(
    const __half* __restrict__ A, const __half* __restrict__ W, int bRows,
    float* __restrict__ outF, const float* __restrict__ bias,
    const float* __restrict__ skipT, __half* __restrict__ Of)
{
    extern __shared__ char smem[];
    const int tid = threadIdx.x, lane = tid & 31, warp = tid >> 5;
    const int mw = warp & 3, nw = warp >> 2;
    const int n0 = blockIdx.x * 64, tl0 = blockIdx.y * 128, zb = blockIdx.z;
    const long long t0 = (long long)zb * LSEQ + tl0;
    const __half* Wp = (EPH == EPH_XPOSE) ? (W + (size_t)(zb >> 1) * 65536) : W;

    float acc[2][4][4];
    #pragma unroll
    for (int i = 0; i < 2; i++)
        #pragma unroll
        for (int j = 0; j < 4; j++)
            #pragma unroll
            for (int c = 0; c < 4; c++) acc[i][j][c] = 0.f;

    const uint32_t sbase = smem_u32(smem);
    const int a_row  = (lane & 7) + ((lane >> 3) & 1) * 8;
    const int a_kadd = (lane >> 4) * 8;
    const int b_row  = (lane & 7) + (lane >> 4) * 8;
    const int b_kadd = ((lane >> 3) & 1) * 8;
    const uint32_t aoff = sbase + 0      + (uint32_t)((mw*32 + a_row)*72 + a_kadd) * 2;
    const uint32_t boff = sbase + TILE_A + (uint32_t)((nw*32 + b_row)*72 + b_kadd) * 2;

    const int lrow = tid >> 3, lc8 = (tid & 7) * 8;

    auto load_chunk = [&](int kc, int stage) {
        const int kofs = kc * 64;
        const uint32_t sb0 = sbase + stage * STGH;
        #pragma unroll
        for (int it = 0; it < 4; it++) {
            int row = lrow + it * 32;
            cp16(sb0 + (uint32_t)(row * 72 + lc8) * 2, A + (t0 + row) * 256 + kofs + lc8, 16);
        }
        #pragma unroll
        for (int it = 0; it < 2; it++) {
            int row = lrow + it * 32;
            int brow = n0 + row;
            int ok = (brow < bRows) ? 16 : 0;
            if (brow >= bRows) brow = bRows - 1;
            cp16(sb0 + TILE_A + (uint32_t)(row * 72 + lc8) * 2,
                 Wp + (size_t)brow * 256 + kofs + lc8, ok);
        }
    };

    auto compute = [&](int stage) {
        const uint32_t sadd = (uint32_t)stage * STGH;
        #pragma unroll
        for (int ks = 0; ks < 4; ks++) {
            const uint32_t k2 = (uint32_t)(ks * 16) * 2;
            uint32_t aF[2][4], bF[2][4];
            #pragma unroll
            for (int i = 0; i < 2; i++) ldmx4(aF[i], aoff + sadd + i*16*144 + k2);
            #pragma unroll
            for (int g = 0; g < 2; g++) ldmx4(bF[g], boff + sadd + g*16*144 + k2);
            #pragma unroll
            for (int i = 0; i < 2; i++)
                #pragma unroll
                for (int g = 0; g < 2; g++)
                    #pragma unroll
                    for (int p = 0; p < 2; p++)
                        mma16816h(acc[i][g*2+p], aF[i], bF[g][2*p], bF[g][2*p+1]);
        }
    };

    // 3-stage pipeline: one barrier per chunk, 2-chunk prefetch depth.
    load_chunk(0, 0);
    asm volatile("cp.async.commit_group;" ::: "memory");
    load_chunk(1, 1);
    asm volatile("cp.async.commit_group;" ::: "memory");
    #pragma unroll
    for (int kc = 0; kc < 4; kc++) {
        if (kc < 3) asm volatile("cp.async.wait_group 1;" ::: "memory");
        else        asm volatile("cp.async.wait_group 0;" ::: "memory");
        __syncthreads();
        compute(kc % 3);
        if (kc < 2) {
            load_chunk(kc + 2, (kc + 2) % 3);
            asm volatile("cp.async.commit_group;" ::: "memory");
        }
    }

    if (EPH == EPH_SKIP) {
        #pragma unroll
        for (int i = 0; i < 2; i++)
            #pragma unroll
            for (int rr = 0; rr < 2; rr++) {
                int tok = tl0 + mw*32 + i*16 + (lane >> 2) + rr*8;
                size_t orow = ((size_t)zb * LSEQ + tok) * 256;
                size_t srow = ((size_t)(zb & 1) * LSEQ + tok) * 256;
                #pragma unroll
                for (int j4 = 0; j4 < 4; j4++) {
                    int n = n0 + nw*32 + j4*8 + 2*(lane & 3);
                    float2 sk = *(const float2*)(skipT + srow + n);
                    __half2 hv;
                    hv.x = __float2half(acc[i][j4][rr*2+0] + sk.x);
                    hv.y = __float2half(acc[i][j4][rr*2+1] + sk.y);
                    *(__half2*)(Of + orow + n) = hv;
                }
            }
    } else {
        // channel-major fp32 (+bias for EPH_BIAS) via smem transpose
        float* sbuf = (float*)smem;
        __syncthreads();
        #pragma unroll
        for (int i = 0; i < 2; i++)
            #pragma unroll
            for (int j4 = 0; j4 < 4; j4++)
                #pragma unroll
                for (int rr = 0; rr < 2; rr++) {
                    int tok = mw*32 + i*16 + (lane >> 2) + rr*8;
                    int nl = nw*32 + j4*8 + 2*(lane & 3);
                    sbuf[nl*132 + tok]     = acc[i][j4][rr*2+0];
                    sbuf[(nl+1)*132 + tok] = acc[i][j4][rr*2+1];
                }
        __syncthreads();
        int row = tid >> 2;
        int n = n0 + row;
        if (n < bRows) {
            float bv = (EPH == EPH_BIAS) ? bias[n] : 0.f;
            const float* srcr = sbuf + row*132;
            float* dstr = outF + ((size_t)zb * bRows + n) * LSEQ + tl0;
            int c0 = (tid & 3) * 4;
            #pragma unroll
            for (int q = 0; q < 8; q++) {
                int col = c0 + q*16;
                float4 v = *(const float4*)(srcr + col);
                v.x += bv; v.y += bv; v.z += bv; v.w += bv;
                *(float4*)(dstr + col) = v;
            }
        }
    }
}

// ---------------- fused fp16 weight converts (4 segments) ----------------
__global__ void whalf4_k(const float* __restrict__ w0, const float* __restrict__ w1,
                         const float* __restrict__ w2, const float* __restrict__ w3,
                         __half* __restrict__ o0, __half* __restrict__ o1,
                         __half* __restrict__ o2, __half* __restrict__ o3)
{
    int seg = blockIdx.y;
    const float* w = seg==0?w0 : seg==1?w1 : seg==2?w2 : w3;
    __half* o = seg==0?o0 : seg==1?o1 : seg==2?o2 : o3;
    int n = (seg < 3) ? 65536 : 307200;
    int i = blockIdx.x * blockDim.x + threadIdx.x;
    if (i < n) o[i] = __float2half(w[i]);
}

// ---------------- transpose input0 -> token-major fp32 ----------------
__global__ void xposeF_k(const float* __restrict__ in, float* __restrict__ out)
{
    __shared__ float t[32][33];
    int b = blockIdx.z;
    int tok0 = blockIdx.x * 32, ch0 = blockIdx.y * 32;
    int lx = threadIdx.x & 31, ly = threadIdx.x >> 5;
    #pragma unroll
    for (int i = 0; i < 4; i++) {
        int ch = ch0 + ly + i*8;
        t[lx][ly + i*8] = in[((size_t)b*256 + ch)*LSEQ + tok0 + lx];
    }
    __syncthreads();
    #pragma unroll
    for (int i = 0; i < 4; i++) {
        int tok = tok0 + ly + i*8;
        out[((size_t)b*LSEQ + tok)*256 + ch0 + lx] = t[ly + i*8][lx];
    }
}

// ---------------- layernorm -> token-major fp16 ----------------
__global__ void __launch_bounds__(256) ln_k(
    const float* __restrict__ in0, const float* __restrict__ in1,
    const float* __restrict__ w0, const float* __restrict__ b0,
    const float* __restrict__ w1, const float* __restrict__ b1,
    __half* __restrict__ snf)
{
    __shared__ float ssum[16][17], s2sum[16][17];
    __shared__ float mrs[2][16];
    __shared__ uint32_t spk[16][132];
    int which = blockIdx.y;
    const float* in = which ? in1 : in0;
    const float* w  = which ? w1  : w0;
    const float* bb = which ? b1  : b0;

    int tid = threadIdx.x;
    int tok = tid & 15, sub = tid >> 4;
    int idx = blockIdx.x * 16 + tok;
    int b = idx >> 12, l = idx & (LSEQ-1);
    const float* p = in + (size_t)b*DIMC*LSEQ + l;

    float vals[16];
    float s = 0.f, s2 = 0.f;
    #pragma unroll
    for (int j = 0; j < 16; j++) {
        float v = p[(size_t)(sub*16 + j)*LSEQ];
        vals[j] = v; s += v; s2 += v*v;
    }
    ssum[sub][tok] = s; s2sum[sub][tok] = s2;
    __syncthreads();
    if (tid < 16) {
        float S = 0.f, S2 = 0.f;
        #pragma unroll
        for (int u = 0; u < 16; u++) { S += ssum[u][tid]; S2 += s2sum[u][tid]; }
        float mean = S * (1.f/DIMC);
        float var  = S2 * (1.f/DIMC) - mean*mean;
        mrs[0][tid] = mean; mrs[1][tid] = rsqrtf(var + EPS_F);
    }
    __syncthreads();
    float mean = mrs[0][tok], rstd = mrs[1][tok];
    #pragma unroll
    for (int j2 = 0; j2 < 8; j2++) {
        int c = sub*16 + j2*2;
        __half2 hv;
        hv.x = __float2half((vals[j2*2]   - mean) * rstd * w[c]   + bb[c]);
        hv.y = __float2half((vals[j2*2+1] - mean) * rstd * w[c+1] + bb[c+1]);
        spk[tok][sub*8 + j2] = *(uint32_t*)&hv;
    }
    __syncthreads();
    int tr = tid >> 4, seg = tid & 15;
    int idx2 = blockIdx.x*16 + tr;
    int b2 = idx2 >> 12, l2 = idx2 & (LSEQ-1);
    size_t obh = ((size_t)(which*2 + b2)*LSEQ + l2) * 256;
    #pragma unroll
    for (int it = 0; it < 2; it++) {
        int s2i = seg + it*16;
        *(uint4*)(snf + obh + s2i*8) = *(uint4*)&spk[tr][s2i*4];
    }
}

// ---------------- depthwise causal conv (K=4) + silu — both dirs ----------------
__global__ void conv_silu_k(const float* __restrict__ x,
                            const float* __restrict__ wf, const float* __restrict__ bf,
                            const float* __restrict__ wb, const float* __restrict__ bbias,
                            float* __restrict__ xc)
{
    int t   = blockIdx.x * blockDim.x + threadIdx.x;
    int bdd = blockIdx.y;
    int dir = bdd >> 9;
    int bd  = bdd & 511;
    int d   = bd & 255;
    const float* w  = dir ? wb : wf;
    const float* bi = dir ? bbias : bf;
    const float* xp = x + (size_t)bd*LSEQ;
    float acc = bi[d];
    #pragma unroll
    for (int k = 0; k < 4; k++) {
        int s = t - 3 + k;
        if (s >= 0) {
            int ph = dir ? (LSEQ-1-s) : s;
            acc += w[d*4+k] * xp[ph];
        }
    }
    xc[(size_t)bdd*LSEQ + t] = acc * sigmoidf_(acc);
}

// ---------------- fp32 SGEMM (xproj / dtproj), per-dir weight select ----------------
enum { EP_NONE=0, EP_SPBIAS=1 };

template<int EP>
__global__ void __launch_bounds__(256) sgemm_k(
    const float* __restrict__ A0, const float* __restrict__ A1, int lda,
    const float* __restrict__ B, int ldb, long long bStride,
    float* __restrict__ C, __half* __restrict__ Ch, int ldc, long long cStride,
    int M, int Kdim,
    const float* __restrict__ bias0, const float* __restrict__ bias1)
{
    __shared__ float As[8][128];
    __shared__ float Bs[8][128];
    int zb = blockIdx.z;
    int dir = zb >> 1;
    const float* A = dir ? A1 : A0;
    const float* bias = dir ? bias1 : bias0;
    B += (size_t)zb * bStride;
    if (EP == EP_SPBIAS) Ch += (size_t)zb * cStride;
    else                 C  += (size_t)zb * cStride;

    int m0 = blockIdx.y * 128;
    int n0 = blockIdx.x * 128;
    int tid = threadIdx.x;
    int ar  = tid >> 1, ac = (tid & 1) << 2;
    int brr = tid >> 5, bc = (tid & 31) << 2;
    int mt0 = (tid >> 4) << 2, nt0 = (tid & 15) << 2;

    unsigned long long acc[8][4];
    #pragma unroll
    for (int i = 0; i < 8; i++)
        #pragma unroll
        for (int j = 0; j < 4; j++) acc[i][j] = 0ull;

    for (int k0 = 0; k0 < Kdim; k0 += 8) {
        float4 a4 = make_float4(0.f,0.f,0.f,0.f);
        int arow = m0 + ar;
        if (arow < M) a4 = *(const float4*)(A + (size_t)arow*lda + (k0 + ac));
        As[ac+0][ar] = a4.x; As[ac+1][ar] = a4.y; As[ac+2][ar] = a4.z; As[ac+3][ar] = a4.w;
        float4 b4 = *(const float4*)(B + (size_t)(k0 + brr)*ldb + (n0 + bc));
        *(float4*)&Bs[brr][bc] = b4;
        __syncthreads();
        #pragma unroll
        for (int kk = 0; kk < 8; kk++) {
            float4 aL = *(const float4*)&As[kk][mt0];
            float4 aH = *(const float4*)&As[kk][mt0+64];
            float av[8] = {aL.x,aL.y,aL.z,aL.w,aH.x,aH.y,aH.z,aH.w};
            unsigned long long b2[4];
            const unsigned long long* bpL = (const unsigned long long*)&Bs[kk][nt0];
            const unsigned long long* bpH = (const unsigned long long*)&Bs[kk][nt0+64];
            b2[0] = bpL[0]; b2[1] = bpL[1]; b2[2] = bpH[0]; b2[3] = bpH[1];
            #pragma unroll
            for (int i = 0; i < 8; i++) {
                unsigned long long a2;
                asm("mov.b64 %0, {%1, %1};" : "=l"(a2) : "f"(av[i]));
                #pragma unroll
                for (int j = 0; j < 4; j++)
                    asm("fma.rn.f32x2 %0, %1, %2, %0;" : "+l"(acc[i][j]) : "l"(a2), "l"(b2[j]));
            }
        }
        __syncthreads();
    }

    #pragma unroll
    for (int i = 0; i < 8; i++) {
        int m = m0 + ((i < 4) ? (mt0 + i) : (64 + mt0 + i - 4));
        if (m >= M) continue;
        float bv = (EP == EP_SPBIAS) ? bias[m] : 0.f;
        #pragma unroll
        for (int j = 0; j < 4; j++) {
            int n = n0 + ((j < 2) ? (nt0 + 2*j) : (64 + nt0 + 2*(j-2)));
            float2 v;
            asm("mov.b64 {%0, %1}, %2;" : "=f"(v.x), "=f"(v.y) : "l"(acc[i][j]));
            if (EP == EP_SPBIAS) {
                __half2 hv;
                hv.x = __float2half(softplusf_(v.x + bv));
                hv.y = __float2half(softplusf_(v.y + bv));
                *(__half2*)(Ch + (size_t)m*ldc + n) = hv;
            } else {
                *(float2*)(C + (size_t)m*ldc + n) = v;
            }
        }
    }
}

// ---------------- chunked selective scan (both dirs in one launch) ----------------
__global__ void __launch_bounds__(256) scanA_k(
    const __half* __restrict__ dt, const float* __restrict__ xc,
    const float* __restrict__ dbl,
    const float* __restrict__ A0, const float* __restrict__ A1,
    float* __restrict__ P, float* __restrict__ S)
{
    __shared__ float sdt[32][65], sx[32][65], sB[8][65];
    int chunk = blockIdx.x, zd = blockIdx.y, d0 = blockIdx.z * 32;
    int dir = zd >> 1, b = zd & 1;
    const float* Alog = dir ? A1 : A0;
    int tid = threadIdx.x;
    size_t base = ((size_t)(zd*DIMC + d0))*LSEQ + chunk*64;
    for (int i = tid; i < 2048; i += 256) {
        int r = i >> 6, c = i & 63;
        sdt[r][c] = __half2float(dt[base + (size_t)r*LSEQ + c]);
        sx [r][c] = xc[base + (size_t)r*LSEQ + c];
    }
    size_t bbase = ((size_t)(zd*32 + 16))*LSEQ + chunk*64;
    for (int i = tid; i < 512; i += 256) {
        int r = i >> 6, c = i & 63;
        sB[r][c] = dbl[bbase + (size_t)r*LSEQ + c];
    }
    __syncthreads();
    int dl = tid >> 3, n = tid & 7;
    float Aa = -__expf(Alog[(d0+dl)*8 + n]);
    float Pv = 1.f, Sv = 0.f;
    #pragma unroll 8
    for (int t = 0; t < 64; t++) {
        float dtv = sdt[dl][t];
        float dA  = __expf(dtv * Aa);
        Sv = Sv*dA + dtv * sx[dl][t] * sB[n][t];
        Pv *= dA;
    }
    size_t o = (size_t)dir*SCN_ + (((size_t)chunk*BATCH + b)*DIMC + d0+dl)*8 + n;
    P[o] = Pv; S[o] = Sv;
}

__global__ void scanB_k(const float* __restrict__ P, const float* __restrict__ S,
                        float* __restrict__ Hi)
{
    int gid = blockIdx.x * blockDim.x + threadIdx.x;
    int dir = gid >> 12, idx = gid & 4095;
    const float* Pd = P + (size_t)dir*SCN_;
    const float* Sd = S + (size_t)dir*SCN_;
    float* Hd = Hi + (size_t)dir*SCN_;
    float h = 0.f;
    for (int c0 = 0; c0 < 64; c0 += 8) {
        float p[8], s[8];
        #pragma unroll
        for (int j = 0; j < 8; j++) {
            size_t o = (size_t)(c0+j)*4096 + idx;
            p[j] = Pd[o]; s[j] = Sd[o];
        }
        #pragma unroll
        for (int j = 0; j < 8; j++) {
            Hd[(size_t)(c0+j)*4096 + idx] = h;
            h = h * p[j] + s[j];
        }
    }
}

__global__ void __launch_bounds__(256) scanC_k(
    const __half* __restrict__ dt, const float* __restrict__ xc,
    const float* __restrict__ dbl,
    const float* __restrict__ A0, const float* __restrict__ A1,
    const float* __restrict__ Hi,
    const float* __restrict__ D0, const float* __restrict__ D1,
    const float* __restrict__ z, float* __restrict__ y)
{
    __shared__ float sdt[32][65], sx[32][65], sB[8][65], sC[8][65];
    __shared__ float sy[32][64];
    int chunk = blockIdx.x, zd = blockIdx.y, d0 = blockIdx.z * 32;
    int dir = zd >> 1, b = zd & 1;
    const float* Alog = dir ? A1 : A0;
    const float* Dp   = dir ? D1 : D0;
    int tid = threadIdx.x;
    size_t base = ((size_t)(zd*DIMC + d0))*LSEQ + chunk*64;
    for (int i = tid; i < 2048; i += 256) {
        int r = i >> 6, c = i & 63;
        sdt[r][c] = __half2float(dt[base + (size_t)r*LSEQ + c]);
        sx [r][c] = xc[base + (size_t)r*LSEQ + c];
    }
    size_t bbase = ((size_t)(zd*32 + 16))*LSEQ + chunk*64;
    size_t cbase = ((size_t)(zd*32 + 24))*LSEQ + chunk*64;
    for (int i = tid; i < 512; i += 256) {
        int r = i >> 6, c = i & 63;
        sB[r][c] = dbl[bbase + (size_t)r*LSEQ + c];
        sC[r][c] = dbl[cbase + (size_t)r*LSEQ + c];
    }
    __syncthreads();
    int dl = tid >> 3, n = tid & 7;
    float Aa = -__expf(Alog[(d0+dl)*8 + n]);
    float h = Hi[(size_t)dir*SCN_ + (((size_t)chunk*BATCH + b)*DIMC + d0+dl)*8 + n];
    for (int t = 0; t < 64; t++) {
        float dtv = sdt[dl][t];
        float dA  = __expf(dtv * Aa);
        h = h*dA + dtv * sx[dl][t] * sB[n][t];
        float yv = h * sC[n][t];
        yv += __shfl_down_sync(0xffffffffu, yv, 4);
        yv += __shfl_down_sync(0xffffffffu, yv, 2);
        yv += __shfl_down_sync(0xffffffffu, yv, 1);
        if (n == 0) sy[dl][t] = yv;
    }
    __syncthreads();
    float* yD = y + (size_t)dir * BATCH*DIMC*LSEQ;
    for (int i = tid; i < 2048; i += 256) {
        int r = i >> 6, c = i & 63;
        int tl = chunk*64 + c;
        int lp = dir ? (LSEQ-1-tl) : tl;
        size_t gi = ((size_t)(b*DIMC + d0 + r))*LSEQ + lp;
        float v = sy[r][c] + sx[r][c]*Dp[d0+r];
        float zz = z[gi];
        yD[gi] = v * zz * sigmoidf_(zz);
    }
}

// ---------------- rmsnorm 3 heads -> token-major fp16 ----------------
__global__ void __launch_bounds__(256) rms3_k(
    const float* __restrict__ yf, const float* __restrict__ yb,
    const float* __restrict__ w,
    __half* __restrict__ ynf)
{
    __shared__ float red[3][16][17];
    __shared__ float rfac[3][16];
    __shared__ uint32_t spk[16][132];
    int tid = threadIdx.x;
    int tok = tid & 15, sub = tid >> 4;
    int idx = blockIdx.x * 16 + tok;
    int b = idx >> 12, l = idx & (LSEQ-1);
    size_t base = (size_t)b*DIMC*LSEQ + l;

    float vf[16], vb[16], wv[16];
    float sa = 0.f, sf = 0.f, sb = 0.f;
    #pragma unroll
    for (int j = 0; j < 16; j++) {
        int c = sub*16 + j;
        float f = yf[base + (size_t)c*LSEQ];
        float bk = yb[base + (size_t)c*LSEQ];
        vf[j] = f; vb[j] = bk; wv[j] = w[c];
        float va = 0.5f*(f + bk);
        sa += va*va; sf += f*f; sb += bk*bk;
    }
    red[0][sub][tok] = sa; red[1][sub][tok] = sf; red[2][sub][tok] = sb;
    __syncthreads();
    if (tid < 48) {
        int hh = tid >> 4, tt = tid & 15;
        float S = 0.f;
        #pragma unroll
        for (int u = 0; u < 16; u++) S += red[hh][u][tt];
        rfac[hh][tt] = rsqrtf(S * (1.f/DIMC) + EPS_F);
    }
    __syncthreads();

    int tr = tid >> 4, seg = tid & 15;
    #pragma unroll 1
    for (int h = 0; h < 3; h++) {
        float r = rfac[h][tok];
        #pragma unroll
        for (int j2 = 0; j2 < 8; j2++) {
            int j = j2*2;
            float v0 = (h == 0) ? 0.5f*(vf[j] + vb[j])     : (h == 1) ? vf[j]   : vb[j];
            float v1 = (h == 0) ? 0.5f*(vf[j+1] + vb[j+1]) : (h == 1) ? vf[j+1] : vb[j+1];
            __half2 hv;
            hv.x = __float2half(v0 * r * wv[j]);
            hv.y = __float2half(v1 * r * wv[j+1]);
            spk[tok][sub*8 + j2] = *(uint32_t*)&hv;
        }
        __syncthreads();
        int idx2 = blockIdx.x*16 + tr;
        int b2 = idx2 >> 12, l2 = idx2 & (LSEQ-1);
        size_t obh = ((size_t)(h*2 + b2)*LSEQ + l2) * 256;
        #pragma unroll
        for (int it = 0; it < 2; it++) {
            int s2 = seg + it*16;
            *(uint4*)(ynf + obh + s2*8) = *(uint4*)&spk[tr][s2*4];
        }
        __syncthreads();
    }
}

// ---------------- launch ----------------
extern "C" void kernel_launch(void* const* d_in, const int* in_sizes, int n_in,
                              void* d_out, int out_size)
{
    (void)in_sizes; (void)n_in; (void)out_size;
    const float* input0      = (const float*)d_in[0];
    const float* input1      = (const float*)d_in[1];
    const float* norm0_w     = (const float*)d_in[2];
    const float* norm0_b     = (const float*)d_in[3];
    const float* norm1_w     = (const float*)d_in[4];
    const float* norm1_b     = (const float*)d_in[5];
    const float* in_proj_w   = (const float*)d_in[6];
    const float* in_projz_w  = (const float*)d_in[7];
    const float* conv1d_w    = (const float*)d_in[8];
    const float* conv1d_bias = (const float*)d_in[9];
    const float* conv1db_w   = (const float*)d_in[10];
    const float* conv1db_bias= (const float*)d_in[11];
    const float* xproj_w     = (const float*)d_in[12];
    const float* xprojb_w    = (const float*)d_in[13];
    const float* dtproj_w    = (const float*)d_in[14];
    const float* dtproj_bias = (const float*)d_in[15];
    const float* dtprojb_w   = (const float*)d_in[16];
    const float* dtprojb_bias= (const float*)d_in[17];
    const float* A_log       = (const float*)d_in[18];
    const float* Ab_log      = (const float*)d_in[19];
    const float* D_p         = (const float*)d_in[20];
    const float* D_b         = (const float*)d_in[21];
    const float* rms_w       = (const float*)d_in[22];
    const float* out_proj_w  = (const float*)d_in[23];
    const float* conv3d_w    = (const float*)d_in[24];
    const float* conv3d_bias = (const float*)d_in[25];
    float* out = (float*)d_out;

    float *xz_, *xc_, *dbl_, *P_, *S_, *Hi_, *y_, *skipT;
    __half *dt_, *snf, *ynf, *of_, *wipzf, *wopf, *wc3f;
    cudaGetSymbolAddress((void**)&xz_,  g_xz);
    cudaGetSymbolAddress((void**)&xc_,  g_xc);
    cudaGetSymbolAddress((void**)&dbl_, g_dbl);
    cudaGetSymbolAddress((void**)&dt_,  g_dt);
    cudaGetSymbolAddress((void**)&P_,   g_P);
    cudaGetSymbolAddress((void**)&S_,   g_S);
    cudaGetSymbolAddress((void**)&Hi_,  g_Hi);
    cudaGetSymbolAddress((void**)&y_,   g_y);
    cudaGetSymbolAddress((void**)&skipT,g_skipT);
    cudaGetSymbolAddress((void**)&snf,  g_snf);
    cudaGetSymbolAddress((void**)&ynf,  g_ynf);
    cudaGetSymbolAddress((void**)&of_,  g_of);
    cudaGetSymbolAddress((void**)&wipzf,g_wipzf);
    cudaGetSymbolAddress((void**)&wopf, g_wopf);
    cudaGetSymbolAddress((void**)&wc3f, g_wc3f);

    float* x_ = xz_;
    float* z_ = xz_ + (size_t)2*DIMC*LSEQ;

    const int TCSMEMH = 3 * STGH;   // 82944 (3-stage), 2 CTAs/SM
    cudaFuncSetAttribute(tcgemmH_k<EPH_XPOSE>, cudaFuncAttributeMaxDynamicSharedMemorySize, TCSMEMH);
    cudaFuncSetAttribute(tcgemmH_k<EPH_SKIP>,  cudaFuncAttributeMaxDynamicSharedMemorySize, TCSMEMH);
    cudaFuncSetAttribute(tcgemmH_k<EPH_BIAS>,  cudaFuncAttributeMaxDynamicSharedMemorySize, TCSMEMH);

    const long long SB  = (long long)DIMC*LSEQ;
    const long long SB32= (long long)32*LSEQ;

    // 0) weight converts (one launch) + skip transpose
    whalf4_k<<<dim3(1200,4), 256>>>(in_proj_w, in_projz_w, out_proj_w, conv3d_w,
                                    wipzf, wipzf + 65536, wopf, wc3f);
    xposeF_k<<<dim3(128,8,2), 256>>>(input0, skipT);

    // 1) layernorms -> token-major fp16 (slabs which*2+b)
    ln_k<<<dim3(512,2), 256>>>(input0, input1, norm0_w, norm0_b, norm1_w, norm1_b, snf);

    // 2) in_proj + in_projz (1-pass fp16, merged z=4) -> channel-major fp32 x|z
    tcgemmH_k<EPH_XPOSE><<<dim3(4,32,4), 256, TCSMEMH>>>(snf, wipzf, 256,
                                                         xz_, nullptr, nullptr, nullptr);

    // 3) conv + silu, both dirs
    conv_silu_k<<<dim3(16,1024), 256>>>(x_, conv1d_w, conv1d_bias, conv1db_w, conv1db_bias,
                                        (float*)xc_);
    // 4) xproj, both dirs
    sgemm_k<EP_NONE><<<dim3(32,1,4), 256>>>(xproj_w, xprojb_w, 256,
                                            xc_, LSEQ, SB, dbl_, nullptr, LSEQ, SB32,
                                            32, 256, nullptr, nullptr);
    // 5) dtproj + softplus -> fp16 dt, both dirs
    sgemm_k<EP_SPBIAS><<<dim3(32,2,4), 256>>>(dtproj_w, dtprojb_w, 16,
                                              dbl_, LSEQ, SB32, nullptr, dt_, LSEQ, SB,
                                              256, 16, dtproj_bias, dtprojb_bias);
    // 6) chunked scan, both dirs
    scanA_k<<<dim3(64,4,8), 256>>>(dt_, xc_, dbl_, A_log, Ab_log, P_, S_);
    scanB_k<<<32, 256>>>(P_, S_, Hi_);
    scanC_k<<<dim3(64,4,8), 256>>>(dt_, xc_, dbl_, A_log, Ab_log, Hi_, D_p, D_b, z_, y_);

    // 7) rmsnorm 3 heads -> token-major fp16
    rms3_k<<<512, 256>>>(y_, y_ + (size_t)BATCH*DIMC*LSEQ, rms_w, ynf);

    // 8) out_proj (+skip) (1-pass fp16) -> token-major fp16 o
    tcgemmH_k<EPH_SKIP><<<dim3(4,32,6), 256, TCSMEMH>>>(ynf, wopf, 256,
                                                        nullptr, nullptr, skipT, of_);

    // 9) conv3d (1-pass fp16, +bias) -> final output (channel-major fp32)
    tcgemmH_k<EPH_BIAS><<<dim3(19,32,6), 256, TCSMEMH>>>(of_, wc3f, 1200,
                                                         out, conv3d_bias, nullptr, nullptr);
}